// round 4
// baseline (speedup 1.0000x reference)
#include <cuda_runtime.h>
#include <cstdint>

#define N_NODES 100000
#define N_EDGES 3200000
#define IN_DIM  512
#define HID     64
#define OUT_DIM 5

// Scratch (allocation-free rule): __device__ globals, device-code refs only.
__device__ __align__(16) float g_dinv[N_NODES];
__device__ __align__(16) float g_hA[(size_t)N_NODES * HID];
__device__ __align__(16) float g_hB[(size_t)N_NODES * HID];

// ---------------- degree / normalization ----------------

__global__ void k_init_deg() {
    int i = blockIdx.x * blockDim.x + threadIdx.x;
    if (i < N_NODES) g_dinv[i] = 1.0f;  // self-loop weight 1
}

__global__ void k_accum_deg(const int* __restrict__ ei,
                            const float* __restrict__ ew) {
    int e = blockIdx.x * blockDim.x + threadIdx.x;
    if (e < N_EDGES) {
        int d = ei[N_EDGES + e];  // dst row of int32 edge_index
        atomicAdd(&g_dinv[d], ew[e]);
    }
}

__global__ void k_rsqrt() {
    int i = blockIdx.x * blockDim.x + threadIdx.x;
    if (i < N_NODES) g_dinv[i] = rsqrtf(g_dinv[i]);  // deg >= 1 always
}

// ---------------- tiled GEMM: g_hA[M,64] = act(A)[M,K] @ B[K,64] ----------------

template <bool RELU_A, bool A_FROM_HB>
__global__ void __launch_bounds__(256)
k_gemm64(const float* __restrict__ Aext, const float* __restrict__ B, int K) {
    const int BM = 128, BN = 64, BK = 32, TM = 8, TN = 4;
    __shared__ float As[BK][BM];   // k-major for broadcasty compute reads
    __shared__ float Bs[BK][BN];

    const float* A = A_FROM_HB ? g_hB : Aext;
    const int M = N_NODES;

    int tid = threadIdx.x;
    int tx = tid & 15;   // cols tx*4 .. tx*4+3
    int ty = tid >> 4;   // rows ty*8 .. ty*8+7
    int rowBase = blockIdx.x * BM;

    float acc[TM][TN];
#pragma unroll
    for (int m = 0; m < TM; m++)
#pragma unroll
        for (int n = 0; n < TN; n++) acc[m][n] = 0.0f;

    for (int k0 = 0; k0 < K; k0 += BK) {
#pragma unroll
        for (int i = 0; i < 4; i++) {
            int idx = tid + i * 256;
            int r   = idx >> 3;
            int k4  = idx & 7;
            int grow = rowBase + r;
            float4 v = make_float4(0.f, 0.f, 0.f, 0.f);
            if (grow < M)
                v = *reinterpret_cast<const float4*>(&A[(size_t)grow * K + k0 + k4 * 4]);
            if (RELU_A) {
                v.x = fmaxf(v.x, 0.f); v.y = fmaxf(v.y, 0.f);
                v.z = fmaxf(v.z, 0.f); v.w = fmaxf(v.w, 0.f);
            }
            As[k4 * 4 + 0][r] = v.x;
            As[k4 * 4 + 1][r] = v.y;
            As[k4 * 4 + 2][r] = v.z;
            As[k4 * 4 + 3][r] = v.w;
        }
#pragma unroll
        for (int i = 0; i < 2; i++) {
            int idx = tid + i * 256;
            int r = idx >> 4;
            int c4 = idx & 15;
            *reinterpret_cast<float4*>(&Bs[r][c4 * 4]) =
                *reinterpret_cast<const float4*>(&B[(size_t)(k0 + r) * BN + c4 * 4]);
        }
        __syncthreads();

#pragma unroll
        for (int k = 0; k < BK; k++) {
            float a[TM], b[TN];
#pragma unroll
            for (int m = 0; m < TM; m++) a[m] = As[k][ty * TM + m];
#pragma unroll
            for (int n = 0; n < TN; n++) b[n] = Bs[k][tx * TN + n];
#pragma unroll
            for (int m = 0; m < TM; m++)
#pragma unroll
                for (int n = 0; n < TN; n++) acc[m][n] = fmaf(a[m], b[n], acc[m][n]);
        }
        __syncthreads();
    }

#pragma unroll
    for (int m = 0; m < TM; m++) {
        int grow = rowBase + ty * TM + m;
        if (grow < M) {
            float4 v = make_float4(acc[m][0], acc[m][1], acc[m][2], acc[m][3]);
            *reinterpret_cast<float4*>(&g_hA[(size_t)grow * BN + tx * TN]) = v;
        }
    }
}

// ------------- aggregation init: g_hB = dinv[n]^2 * g_hA[n] + bias -------------

__global__ void k_init_agg(const float* __restrict__ bias) {
    int i = blockIdx.x * blockDim.x + threadIdx.x;  // over N_NODES*16 float4s
    if (i >= N_NODES * (HID / 4)) return;
    int n = i >> 4;
    int l = i & 15;
    float di = g_dinv[n];
    float c = di * di;
    float4 v = *reinterpret_cast<const float4*>(&g_hA[(size_t)n * HID + l * 4]);
    float4 b = *reinterpret_cast<const float4*>(&bias[l * 4]);
    v.x = fmaf(v.x, c, b.x);
    v.y = fmaf(v.y, c, b.y);
    v.z = fmaf(v.z, c, b.z);
    v.w = fmaf(v.w, c, b.w);
    *reinterpret_cast<float4*>(&g_hB[(size_t)n * HID + l * 4]) = v;
}

// -------- edge scatter: g_hB[dst] += norm_e * g_hA[src] --------
// 16 threads/edge. Each thread owns columns {lane, lane+16, lane+32, lane+48}:
// per step, lanes 0..15 touch 16 consecutive floats (coalesced), while each
// thread's own atomics are 64B apart so the compiler cannot fuse them into a
// vector reduction. Pure scalar RED.E.ADD.F32 path.

__global__ void __launch_bounds__(256)
k_scatter(const int* __restrict__ ei, const float* __restrict__ ew) {
    long long t = (long long)blockIdx.x * blockDim.x + threadIdx.x;
    int e = (int)(t >> 4);
    int lane = (int)(t & 15);
    if (e >= N_EDGES) return;
    int s = ei[e];
    int d = ei[N_EDGES + e];
    float c = g_dinv[s] * ew[e] * g_dinv[d];
    const float* src = &g_hA[(size_t)s * HID];
    float*       dst = &g_hB[(size_t)d * HID];
#pragma unroll
    for (int j = 0; j < 4; j++) {
        int col = lane + j * 16;
        atomicAdd(&dst[col], src[col] * c);
    }
}

// ---------------- final FC: out[n] = relu(g_hB[n]) @ Wfc + bfc ----------------

__global__ void k_fc(const float* __restrict__ W, const float* __restrict__ b,
                     float* __restrict__ out) {
    __shared__ float Ws[HID * OUT_DIM];
    for (int i = threadIdx.x; i < HID * OUT_DIM; i += blockDim.x) Ws[i] = W[i];
    __syncthreads();
    int n = blockIdx.x * blockDim.x + threadIdx.x;
    if (n >= N_NODES) return;
    float acc[OUT_DIM];
#pragma unroll
    for (int k = 0; k < OUT_DIM; k++) acc[k] = b[k];
    const float* hr = &g_hB[(size_t)n * HID];
#pragma unroll 4
    for (int dIdx = 0; dIdx < HID; dIdx++) {
        float v = fmaxf(hr[dIdx], 0.0f);
#pragma unroll
        for (int k = 0; k < OUT_DIM; k++) acc[k] = fmaf(v, Ws[dIdx * OUT_DIM + k], acc[k]);
    }
#pragma unroll
    for (int k = 0; k < OUT_DIM; k++) out[(size_t)n * OUT_DIM + k] = acc[k];
}

// ---------------- launcher: kernel launches ONLY ----------------

extern "C" void kernel_launch(void* const* d_in, const int* in_sizes, int n_in,
                              void* d_out, int out_size) {
    const float* x   = (const float*)d_in[0];
    const int*   ei  = (const int*)d_in[1];    // int32! (JAX x64 disabled)
    const float* ew  = (const float*)d_in[2];
    const float* W1  = (const float*)d_in[3];
    const float* b1  = (const float*)d_in[4];
    const float* W2  = (const float*)d_in[5];
    const float* b2  = (const float*)d_in[6];
    const float* Wfc = (const float*)d_in[7];
    const float* bfc = (const float*)d_in[8];
    float* out = (float*)d_out;

    const int T = 256;
    int gbN    = (N_NODES + T - 1) / T;
    int gbE    = (N_EDGES + T - 1) / T;
    int gbV    = (N_NODES * (HID / 4) + T - 1) / T;
    int gbSc   = (int)(((long long)N_EDGES * 16 + T - 1) / T);
    int gbGemm = (N_NODES + 127) / 128;

    // normalization coefficients
    k_init_deg<<<gbN, T>>>();
    k_accum_deg<<<gbE, T>>>(ei, ew);
    k_rsqrt<<<gbN, T>>>();

    // layer 1
    k_gemm64<false, false><<<gbGemm, T>>>(x, W1, IN_DIM);
    k_init_agg<<<gbV, T>>>(b1);
    k_scatter<<<gbSc, T>>>(ei, ew);

    // layer 2 (ReLU of layer-1 output applied on GEMM A-load)
    k_gemm64<true, true><<<gbGemm, T>>>(nullptr, W2, HID);
    k_init_agg<<<gbV, T>>>(b2);
    k_scatter<<<gbSc, T>>>(ei, ew);

    // final classifier (ReLU applied on load)
    k_fc<<<gbN, T>>>(Wfc, bfc, out);
}

// round 5
// speedup vs baseline: 1.2324x; 1.2324x over previous
#include <cuda_runtime.h>
#include <cstdint>

#define N_NODES 100000
#define N_EDGES 3200000
#define IN_DIM  512
#define HID     64
#define OUT_DIM 5

// Scratch (allocation-free rule): __device__ globals, device-code refs only.
__device__ __align__(16) float g_dinv[N_NODES];
__device__ __align__(16) float g_hA[(size_t)N_NODES * HID];
__device__ __align__(16) float g_hB[(size_t)N_NODES * HID];

// ---------------- degree / normalization ----------------

__global__ void k_init_deg() {
    int i = blockIdx.x * blockDim.x + threadIdx.x;
    if (i < N_NODES) g_dinv[i] = 1.0f;  // self-loop weight 1
}

__global__ void k_accum_deg(const int* __restrict__ ei,
                            const float* __restrict__ ew) {
    int e = blockIdx.x * blockDim.x + threadIdx.x;
    if (e < N_EDGES) {
        int d = ei[N_EDGES + e];
        atomicAdd(&g_dinv[d], ew[e]);
    }
}

__global__ void k_rsqrt() {
    int i = blockIdx.x * blockDim.x + threadIdx.x;
    if (i < N_NODES) g_dinv[i] = rsqrtf(g_dinv[i]);  // deg >= 1 always
}

// ---- tiled GEMM + fused aggregation-init epilogue ----
// g_hA[M,64] = act(A)[M,K] @ B[K,64]
// g_hB[M,64] = dinv[m]^2 * g_hA[m] + bias      (self-loop term + bias)

template <bool RELU_A, bool A_FROM_HB>
__global__ void __launch_bounds__(256)
k_gemm64(const float* __restrict__ Aext, const float* __restrict__ B,
         const float* __restrict__ bias, int K) {
    const int BM = 128, BN = 64, BK = 32, TM = 8, TN = 4;
    __shared__ float As[BK][BM];   // k-major for broadcasty compute reads
    __shared__ float Bs[BK][BN];

    const float* A = A_FROM_HB ? g_hB : Aext;
    const int M = N_NODES;

    int tid = threadIdx.x;
    int tx = tid & 15;   // cols tx*4 .. tx*4+3
    int ty = tid >> 4;   // rows ty*8 .. ty*8+7
    int rowBase = blockIdx.x * BM;

    float acc[TM][TN];
#pragma unroll
    for (int m = 0; m < TM; m++)
#pragma unroll
        for (int n = 0; n < TN; n++) acc[m][n] = 0.0f;

    for (int k0 = 0; k0 < K; k0 += BK) {
#pragma unroll
        for (int i = 0; i < 4; i++) {
            int idx = tid + i * 256;
            int r   = idx >> 3;
            int k4  = idx & 7;
            int grow = rowBase + r;
            float4 v = make_float4(0.f, 0.f, 0.f, 0.f);
            if (grow < M)
                v = *reinterpret_cast<const float4*>(&A[(size_t)grow * K + k0 + k4 * 4]);
            if (RELU_A) {
                v.x = fmaxf(v.x, 0.f); v.y = fmaxf(v.y, 0.f);
                v.z = fmaxf(v.z, 0.f); v.w = fmaxf(v.w, 0.f);
            }
            As[k4 * 4 + 0][r] = v.x;
            As[k4 * 4 + 1][r] = v.y;
            As[k4 * 4 + 2][r] = v.z;
            As[k4 * 4 + 3][r] = v.w;
        }
#pragma unroll
        for (int i = 0; i < 2; i++) {
            int idx = tid + i * 256;
            int r = idx >> 4;
            int c4 = idx & 15;
            *reinterpret_cast<float4*>(&Bs[r][c4 * 4]) =
                *reinterpret_cast<const float4*>(&B[(size_t)(k0 + r) * BN + c4 * 4]);
        }
        __syncthreads();

#pragma unroll
        for (int k = 0; k < BK; k++) {
            float a[TM], b[TN];
#pragma unroll
            for (int m = 0; m < TM; m++) a[m] = As[k][ty * TM + m];
#pragma unroll
            for (int n = 0; n < TN; n++) b[n] = Bs[k][tx * TN + n];
#pragma unroll
            for (int m = 0; m < TM; m++)
#pragma unroll
                for (int n = 0; n < TN; n++) acc[m][n] = fmaf(a[m], b[n], acc[m][n]);
        }
        __syncthreads();
    }

    // Fused epilogue: write raw h (gather source) AND the aggregation
    // accumulator init dinv^2*h + bias (self-loop contribution).
    float4 bb = *reinterpret_cast<const float4*>(&bias[tx * TN]);
#pragma unroll
    for (int m = 0; m < TM; m++) {
        int grow = rowBase + ty * TM + m;
        if (grow < M) {
            float4 v = make_float4(acc[m][0], acc[m][1], acc[m][2], acc[m][3]);
            *reinterpret_cast<float4*>(&g_hA[(size_t)grow * BN + tx * TN]) = v;
            float di = g_dinv[grow];
            float c = di * di;
            float4 w;
            w.x = fmaf(v.x, c, bb.x);
            w.y = fmaf(v.y, c, bb.y);
            w.z = fmaf(v.z, c, bb.z);
            w.w = fmaf(v.w, c, bb.w);
            *reinterpret_cast<float4*>(&g_hB[(size_t)grow * BN + tx * TN]) = w;
        }
    }
}

// -------- edge scatter: g_hB[dst] += norm_e * g_hA[src] --------
// 16 threads/edge, one float4 gather + one VECTOR reduction each.
// red.global.add.v4.f32: 4x fewer L2 atomic transactions than scalar.

__global__ void __launch_bounds__(256)
k_scatter(const int* __restrict__ ei, const float* __restrict__ ew) {
    long long t = (long long)blockIdx.x * blockDim.x + threadIdx.x;
    int e = (int)(t >> 4);
    int lane = (int)(t & 15);
    if (e >= N_EDGES) return;
    int s = ei[e];
    int d = ei[N_EDGES + e];
    float c = g_dinv[s] * ew[e] * g_dinv[d];
    float4 v = *reinterpret_cast<const float4*>(&g_hA[(size_t)s * HID + lane * 4]);
    float* p = &g_hB[(size_t)d * HID + lane * 4];
    asm volatile("red.global.add.v4.f32 [%0], {%1, %2, %3, %4};"
                 :: "l"(p), "f"(v.x * c), "f"(v.y * c), "f"(v.z * c), "f"(v.w * c)
                 : "memory");
}

// ---------------- final FC: out[n] = relu(g_hB[n]) @ Wfc + bfc ----------------

__global__ void k_fc(const float* __restrict__ W, const float* __restrict__ b,
                     float* __restrict__ out) {
    __shared__ float Ws[HID * OUT_DIM];
    for (int i = threadIdx.x; i < HID * OUT_DIM; i += blockDim.x) Ws[i] = W[i];
    __syncthreads();
    int n = blockIdx.x * blockDim.x + threadIdx.x;
    if (n >= N_NODES) return;
    float acc[OUT_DIM];
#pragma unroll
    for (int k = 0; k < OUT_DIM; k++) acc[k] = b[k];
    const float* hr = &g_hB[(size_t)n * HID];
#pragma unroll 4
    for (int dIdx = 0; dIdx < HID; dIdx++) {
        float v = fmaxf(hr[dIdx], 0.0f);
#pragma unroll
        for (int k = 0; k < OUT_DIM; k++) acc[k] = fmaf(v, Ws[dIdx * OUT_DIM + k], acc[k]);
    }
#pragma unroll
    for (int k = 0; k < OUT_DIM; k++) out[(size_t)n * OUT_DIM + k] = acc[k];
}

// ---------------- launcher: kernel launches ONLY ----------------

extern "C" void kernel_launch(void* const* d_in, const int* in_sizes, int n_in,
                              void* d_out, int out_size) {
    const float* x   = (const float*)d_in[0];
    const int*   ei  = (const int*)d_in[1];    // int32 (JAX x64 disabled)
    const float* ew  = (const float*)d_in[2];
    const float* W1  = (const float*)d_in[3];
    const float* b1  = (const float*)d_in[4];
    const float* W2  = (const float*)d_in[5];
    const float* b2  = (const float*)d_in[6];
    const float* Wfc = (const float*)d_in[7];
    const float* bfc = (const float*)d_in[8];
    float* out = (float*)d_out;

    const int T = 256;
    int gbN    = (N_NODES + T - 1) / T;
    int gbE    = (N_EDGES + T - 1) / T;
    int gbSc   = (int)(((long long)N_EDGES * 16 + T - 1) / T);
    int gbGemm = (N_NODES + 127) / 128;

    // normalization coefficients
    k_init_deg<<<gbN, T>>>();
    k_accum_deg<<<gbE, T>>>(ei, ew);
    k_rsqrt<<<gbN, T>>>();

    // layer 1 (GEMM writes hA and hB = dinv^2*hA + b1)
    k_gemm64<false, false><<<gbGemm, T>>>(x, W1, b1, IN_DIM);
    k_scatter<<<gbSc, T>>>(ei, ew);

    // layer 2 (ReLU of layer-1 output applied on GEMM A-load)
    k_gemm64<true, true><<<gbGemm, T>>>(nullptr, W2, b2, HID);
    k_scatter<<<gbSc, T>>>(ei, ew);

    // final classifier (ReLU applied on load)
    k_fc<<<gbN, T>>>(Wfc, bfc, out);
}

// round 6
// speedup vs baseline: 1.4721x; 1.1945x over previous
#include <cuda_runtime.h>
#include <cstdint>

#define N_NODES 100000
#define N_EDGES 3200000
#define IN_DIM  512
#define HID     64
#define OUT_DIM 5

// Scratch (allocation-free rule): __device__ globals, device-code refs only.
__device__ __align__(16) float g_dinv[N_NODES];
__device__ __align__(16) float g_hA[(size_t)N_NODES * HID];
__device__ __align__(16) float g_hB[(size_t)N_NODES * HID];
// CSR (dst-binned), rebuilt each launch, shared by both layers.
__device__ int  g_cnt[N_NODES];
__device__ int  g_rowptr[N_NODES + 1];
__device__ int  g_cursor[N_NODES];
__device__ __align__(8) int2 g_epack[N_EDGES];   // {src, bitcast(norm)}

// ---------------- degree + incoming-count ----------------

__global__ void k_init() {
    int i = blockIdx.x * blockDim.x + threadIdx.x;
    if (i < N_NODES) { g_dinv[i] = 1.0f; g_cnt[i] = 0; }
}

__global__ void k_accum_deg(const int* __restrict__ ei,
                            const float* __restrict__ ew) {
    int e = blockIdx.x * blockDim.x + threadIdx.x;
    if (e < N_EDGES) {
        int d = ei[N_EDGES + e];
        atomicAdd(&g_dinv[d], ew[e]);
        atomicAdd(&g_cnt[d], 1);
    }
}

__global__ void k_rsqrt() {
    int i = blockIdx.x * blockDim.x + threadIdx.x;
    if (i < N_NODES) g_dinv[i] = rsqrtf(g_dinv[i]);  // deg >= 1 always
}

// ---------------- single-block prefix scan: rowptr, cursor ----------------

#define SCAN_T 1024
__global__ void __launch_bounds__(SCAN_T) k_scan() {
    __shared__ int warp_sums[32];
    __shared__ int s_carry;
    int tid = threadIdx.x, lane = tid & 31, wid = tid >> 5;
    if (tid == 0) { s_carry = 0; g_rowptr[0] = 0; }
    __syncthreads();
    for (int base = 0; base < N_NODES; base += SCAN_T) {
        int i = base + tid;
        int v = (i < N_NODES) ? g_cnt[i] : 0;
        int x = v;
#pragma unroll
        for (int o = 1; o < 32; o <<= 1) {
            int y = __shfl_up_sync(~0u, x, o);
            if (lane >= o) x += y;
        }
        if (lane == 31) warp_sums[wid] = x;
        __syncthreads();
        if (wid == 0) {
            int w = warp_sums[lane];
#pragma unroll
            for (int o = 1; o < 32; o <<= 1) {
                int y = __shfl_up_sync(~0u, w, o);
                if (lane >= o) w += y;
            }
            warp_sums[lane] = w;
        }
        __syncthreads();
        int incl = x + (wid > 0 ? warp_sums[wid - 1] : 0) + s_carry;
        if (i < N_NODES) {
            g_rowptr[i + 1] = incl;
            g_cursor[i] = incl - v;   // exclusive start
        }
        __syncthreads();
        if (tid == SCAN_T - 1) s_carry = incl;
        __syncthreads();
    }
}

// ---------------- CSR fill: pack (src, norm) per dst bin ----------------

__global__ void k_fill(const int* __restrict__ ei, const float* __restrict__ ew) {
    int e = blockIdx.x * blockDim.x + threadIdx.x;
    if (e >= N_EDGES) return;
    int s = ei[e];
    int d = ei[N_EDGES + e];
    float nm = g_dinv[s] * ew[e] * g_dinv[d];
    int pos = atomicAdd(&g_cursor[d], 1);
    g_epack[pos] = make_int2(s, __float_as_int(nm));
}

// ---------------- tiled GEMM: g_hA[M,64] = act(A)[M,K] @ B[K,64] ----------------

template <bool RELU_A, bool A_FROM_HB>
__global__ void __launch_bounds__(256)
k_gemm64(const float* __restrict__ Aext, const float* __restrict__ B, int K) {
    const int BM = 128, BN = 64, BK = 32, TM = 8, TN = 4;
    __shared__ float As[BK][BM];
    __shared__ float Bs[BK][BN];

    const float* A = A_FROM_HB ? g_hB : Aext;
    const int M = N_NODES;

    int tid = threadIdx.x;
    int tx = tid & 15;
    int ty = tid >> 4;
    int rowBase = blockIdx.x * BM;

    float acc[TM][TN];
#pragma unroll
    for (int m = 0; m < TM; m++)
#pragma unroll
        for (int n = 0; n < TN; n++) acc[m][n] = 0.0f;

    for (int k0 = 0; k0 < K; k0 += BK) {
#pragma unroll
        for (int i = 0; i < 4; i++) {
            int idx = tid + i * 256;
            int r   = idx >> 3;
            int k4  = idx & 7;
            int grow = rowBase + r;
            float4 v = make_float4(0.f, 0.f, 0.f, 0.f);
            if (grow < M)
                v = *reinterpret_cast<const float4*>(&A[(size_t)grow * K + k0 + k4 * 4]);
            if (RELU_A) {
                v.x = fmaxf(v.x, 0.f); v.y = fmaxf(v.y, 0.f);
                v.z = fmaxf(v.z, 0.f); v.w = fmaxf(v.w, 0.f);
            }
            As[k4 * 4 + 0][r] = v.x;
            As[k4 * 4 + 1][r] = v.y;
            As[k4 * 4 + 2][r] = v.z;
            As[k4 * 4 + 3][r] = v.w;
        }
#pragma unroll
        for (int i = 0; i < 2; i++) {
            int idx = tid + i * 256;
            int r = idx >> 4;
            int c4 = idx & 15;
            *reinterpret_cast<float4*>(&Bs[r][c4 * 4]) =
                *reinterpret_cast<const float4*>(&B[(size_t)(k0 + r) * BN + c4 * 4]);
        }
        __syncthreads();

#pragma unroll
        for (int k = 0; k < BK; k++) {
            float a[TM], b[TN];
#pragma unroll
            for (int m = 0; m < TM; m++) a[m] = As[k][ty * TM + m];
#pragma unroll
            for (int n = 0; n < TN; n++) b[n] = Bs[k][tx * TN + n];
#pragma unroll
            for (int m = 0; m < TM; m++)
#pragma unroll
                for (int n = 0; n < TN; n++) acc[m][n] = fmaf(a[m], b[n], acc[m][n]);
        }
        __syncthreads();
    }

#pragma unroll
    for (int m = 0; m < TM; m++) {
        int grow = rowBase + ty * TM + m;
        if (grow < M) {
            float4 v = make_float4(acc[m][0], acc[m][1], acc[m][2], acc[m][3]);
            *reinterpret_cast<float4*>(&g_hA[(size_t)grow * BN + tx * TN]) = v;
        }
    }
}

// -------- pull aggregation: one warp per dst row --------
// acc = dinv^2 * hA[row] + bias + sum_e norm_e * hA[src_e]
// FUSE_FC: instead of writing hB, apply ReLU and produce out = h @ Wfc + bfc.

template <bool FUSE_FC>
__global__ void __launch_bounds__(256)
k_pull(const float* __restrict__ bias, const float* __restrict__ Wfc,
       const float* __restrict__ bfc, float* __restrict__ out) {
    int lane = threadIdx.x & 31;
    int row = blockIdx.x * 8 + (threadIdx.x >> 5);
    if (row >= N_NODES) return;

    float di = g_dinv[row];
    float c = di * di;
    const float* hr = &g_hA[(size_t)row * HID];
    float a0 = fmaf(hr[lane],      c, bias[lane]);
    float a1 = fmaf(hr[lane + 32], c, bias[lane + 32]);

    int start = g_rowptr[row];
    int end   = g_rowptr[row + 1];
    for (int i = start; i < end; i += 32) {
        int n = min(32, end - i);
        int2 pk = make_int2(0, 0);
        if (i + lane < end) pk = g_epack[i + lane];
        for (int j = 0; j < n; j++) {
            int   s  = __shfl_sync(~0u, pk.x, j);
            float nm = __int_as_float(__shfl_sync(~0u, pk.y, j));
            const float* hs = &g_hA[(size_t)s * HID];
            a0 = fmaf(hs[lane],      nm, a0);
            a1 = fmaf(hs[lane + 32], nm, a1);
        }
    }

    if (!FUSE_FC) {
        g_hB[(size_t)row * HID + lane]      = a0;
        g_hB[(size_t)row * HID + lane + 32] = a1;
    } else {
        a0 = fmaxf(a0, 0.f);
        a1 = fmaxf(a1, 0.f);
        float res[OUT_DIM];
#pragma unroll
        for (int k = 0; k < OUT_DIM; k++) {
            float p = a0 * __ldg(&Wfc[lane * OUT_DIM + k]) +
                      a1 * __ldg(&Wfc[(lane + 32) * OUT_DIM + k]);
#pragma unroll
            for (int o = 16; o > 0; o >>= 1) p += __shfl_xor_sync(~0u, p, o);
            res[k] = p;
        }
        if (lane < OUT_DIM)
            out[(size_t)row * OUT_DIM + lane] = res[lane] + bfc[lane];
    }
}

// ---------------- launcher: kernel launches ONLY ----------------

extern "C" void kernel_launch(void* const* d_in, const int* in_sizes, int n_in,
                              void* d_out, int out_size) {
    const float* x   = (const float*)d_in[0];
    const int*   ei  = (const int*)d_in[1];    // int32 (JAX x64 disabled)
    const float* ew  = (const float*)d_in[2];
    const float* W1  = (const float*)d_in[3];
    const float* b1  = (const float*)d_in[4];
    const float* W2  = (const float*)d_in[5];
    const float* b2  = (const float*)d_in[6];
    const float* Wfc = (const float*)d_in[7];
    const float* bfc = (const float*)d_in[8];
    float* out = (float*)d_out;

    const int T = 256;
    int gbN    = (N_NODES + T - 1) / T;
    int gbE    = (N_EDGES + T - 1) / T;
    int gbGemm = (N_NODES + 127) / 128;
    int gbPull = (N_NODES + 7) / 8;

    // degree + CSR build (shared by both layers)
    k_init<<<gbN, T>>>();
    k_accum_deg<<<gbE, T>>>(ei, ew);
    k_rsqrt<<<gbN, T>>>();
    k_scan<<<1, SCAN_T>>>();
    k_fill<<<gbE, T>>>(ei, ew);

    // layer 1
    k_gemm64<false, false><<<gbGemm, T>>>(x, W1, IN_DIM);
    k_pull<false><<<gbPull, T>>>(b1, nullptr, nullptr, nullptr);

    // layer 2 + fused FC
    k_gemm64<true, true><<<gbGemm, T>>>(nullptr, W2, HID);
    k_pull<true><<<gbPull, T>>>(b2, Wfc, bfc, out);
}

// round 7
// speedup vs baseline: 1.6286x; 1.1063x over previous
#include <cuda_runtime.h>
#include <cstdint>

#define N_NODES 100000
#define N_EDGES 3200000
#define IN_DIM  512
#define HID     64
#define OUT_DIM 5

#define SB 1024
#define NBLK ((N_NODES + SB - 1) / SB)   // 98

// Scratch (allocation-free rule): __device__ globals, device-code refs only.
__device__ __align__(16) float g_dinv[N_NODES];
__device__ __align__(16) float g_hA[(size_t)N_NODES * HID];
__device__ __align__(16) float g_hB[(size_t)N_NODES * HID];
// CSR (dst-binned), rebuilt each launch, shared by both layers.
__device__ int  g_cnt[N_NODES];
__device__ int  g_rowptr[N_NODES + 1];
__device__ int  g_cursor[N_NODES];
__device__ int  g_bsum[NBLK];
__device__ __align__(8) int2 g_epack[N_EDGES];   // {src, bitcast(norm)}

// ---------------- degree + incoming-count ----------------

__global__ void k_init() {
    int i = blockIdx.x * blockDim.x + threadIdx.x;
    if (i < N_NODES) { g_dinv[i] = 1.0f; g_cnt[i] = 0; }
}

__global__ void k_accum_deg(const int* __restrict__ ei,
                            const float* __restrict__ ew) {
    int e = blockIdx.x * blockDim.x + threadIdx.x;
    if (e < N_EDGES) {
        int d = ei[N_EDGES + e];
        atomicAdd(&g_dinv[d], ew[e]);
        atomicAdd(&g_cnt[d], 1);
    }
}

__global__ void k_rsqrt() {
    int i = blockIdx.x * blockDim.x + threadIdx.x;
    if (i < N_NODES) g_dinv[i] = rsqrtf(g_dinv[i]);  // deg >= 1 always
}

// ---------------- multi-block 3-phase prefix scan ----------------

__global__ void __launch_bounds__(SB) k_scan1() {
    __shared__ int ws[32];
    int tid = threadIdx.x, lane = tid & 31, wid = tid >> 5;
    int i = blockIdx.x * SB + tid;
    int v = (i < N_NODES) ? g_cnt[i] : 0;
    int x = v;
#pragma unroll
    for (int o = 1; o < 32; o <<= 1) {
        int y = __shfl_up_sync(~0u, x, o);
        if (lane >= o) x += y;
    }
    if (lane == 31) ws[wid] = x;
    __syncthreads();
    if (wid == 0) {
        int w = ws[lane];
#pragma unroll
        for (int o = 1; o < 32; o <<= 1) {
            int y = __shfl_up_sync(~0u, w, o);
            if (lane >= o) w += y;
        }
        ws[lane] = w;
    }
    __syncthreads();
    int incl = x + (wid > 0 ? ws[wid - 1] : 0);
    if (i < N_NODES) g_rowptr[i + 1] = incl;       // un-offset local inclusive
    if (tid == SB - 1) g_bsum[blockIdx.x] = incl;  // block total
}

__global__ void k_scan2() {   // ONE warp: exclusive scan of 98 block sums
    int lane = threadIdx.x;
    int carry = 0;
    for (int base = 0; base < NBLK; base += 32) {
        int v = (base + lane < NBLK) ? g_bsum[base + lane] : 0;
        int x = v;
#pragma unroll
        for (int o = 1; o < 32; o <<= 1) {
            int y = __shfl_up_sync(~0u, x, o);
            if (lane >= o) x += y;
        }
        if (base + lane < NBLK) g_bsum[base + lane] = x - v + carry;
        carry += __shfl_sync(~0u, x, 31);
    }
}

__global__ void __launch_bounds__(SB) k_scan3() {
    int i = blockIdx.x * SB + threadIdx.x;
    if (i >= N_NODES) return;
    int off = g_bsum[i >> 10];                     // SB == 1024
    int r = g_rowptr[i + 1] + off;
    g_rowptr[i + 1] = r;
    g_cursor[i] = r - g_cnt[i];
    if (i == 0) g_rowptr[0] = 0;
}

// ---------------- CSR fill: pack (src, norm) per dst bin ----------------

__global__ void k_fill(const int* __restrict__ ei, const float* __restrict__ ew) {
    int e = blockIdx.x * blockDim.x + threadIdx.x;
    if (e >= N_EDGES) return;
    int s = ei[e];
    int d = ei[N_EDGES + e];
    float nm = g_dinv[s] * ew[e] * g_dinv[d];
    int pos = atomicAdd(&g_cursor[d], 1);
    g_epack[pos] = make_int2(s, __float_as_int(nm));
}

// ------- tiled GEMM with register-prefetch double buffering -------
// g_hA[M,64] = act(A)[M,K] @ B[K,64]

template <bool RELU_A, bool A_FROM_HB>
__global__ void __launch_bounds__(256)
k_gemm64(const float* __restrict__ Aext, const float* __restrict__ B, int K) {
    const int BM = 128, BN = 64, BK = 32, TM = 8, TN = 4;
    __shared__ float As[BK][BM];
    __shared__ float Bs[BK][BN];

    const float* A = A_FROM_HB ? g_hB : Aext;
    const int M = N_NODES;

    int tid = threadIdx.x;
    int tx = tid & 15;
    int ty = tid >> 4;
    int rowBase = blockIdx.x * BM;

    // per-thread load coordinates (invariant across k0)
    int lr[4], lk4[4];
#pragma unroll
    for (int i = 0; i < 4; i++) {
        int idx = tid + i * 256;
        lr[i]  = idx >> 3;
        lk4[i] = idx & 7;
    }
    int br[2], bc4[2];
#pragma unroll
    for (int i = 0; i < 2; i++) {
        int idx = tid + i * 256;
        br[i]  = idx >> 4;
        bc4[i] = idx & 15;
    }

    float4 ra[4], rb[2];
    auto loadTiles = [&](int k0) {
#pragma unroll
        for (int i = 0; i < 4; i++) {
            int grow = rowBase + lr[i];
            float4 v = make_float4(0.f, 0.f, 0.f, 0.f);
            if (grow < M)
                v = *reinterpret_cast<const float4*>(&A[(size_t)grow * K + k0 + lk4[i] * 4]);
            if (RELU_A) {
                v.x = fmaxf(v.x, 0.f); v.y = fmaxf(v.y, 0.f);
                v.z = fmaxf(v.z, 0.f); v.w = fmaxf(v.w, 0.f);
            }
            ra[i] = v;
        }
#pragma unroll
        for (int i = 0; i < 2; i++)
            rb[i] = *reinterpret_cast<const float4*>(&B[(size_t)(k0 + br[i]) * BN + bc4[i] * 4]);
    };

    float acc[TM][TN];
#pragma unroll
    for (int m = 0; m < TM; m++)
#pragma unroll
        for (int n = 0; n < TN; n++) acc[m][n] = 0.0f;

    loadTiles(0);

    for (int k0 = 0; k0 < K; k0 += BK) {
        // commit prefetched regs to smem
#pragma unroll
        for (int i = 0; i < 4; i++) {
            As[lk4[i] * 4 + 0][lr[i]] = ra[i].x;
            As[lk4[i] * 4 + 1][lr[i]] = ra[i].y;
            As[lk4[i] * 4 + 2][lr[i]] = ra[i].z;
            As[lk4[i] * 4 + 3][lr[i]] = ra[i].w;
        }
#pragma unroll
        for (int i = 0; i < 2; i++)
            *reinterpret_cast<float4*>(&Bs[br[i]][bc4[i] * 4]) = rb[i];
        __syncthreads();

        if (k0 + BK < K) loadTiles(k0 + BK);   // overlap with compute below

#pragma unroll
        for (int k = 0; k < BK; k++) {
            float a[TM], b[TN];
#pragma unroll
            for (int m = 0; m < TM; m++) a[m] = As[k][ty * TM + m];
#pragma unroll
            for (int n = 0; n < TN; n++) b[n] = Bs[k][tx * TN + n];
#pragma unroll
            for (int m = 0; m < TM; m++)
#pragma unroll
                for (int n = 0; n < TN; n++) acc[m][n] = fmaf(a[m], b[n], acc[m][n]);
        }
        __syncthreads();
    }

#pragma unroll
    for (int m = 0; m < TM; m++) {
        int grow = rowBase + ty * TM + m;
        if (grow < M) {
            float4 v = make_float4(acc[m][0], acc[m][1], acc[m][2], acc[m][3]);
            *reinterpret_cast<float4*>(&g_hA[(size_t)grow * BN + tx * TN]) = v;
        }
    }
}

// -------- pull aggregation: one warp per dst row --------
// acc = dinv^2 * hA[row] + bias + sum_e norm_e * hA[src_e]
// FUSE_FC: apply ReLU and produce out = h @ Wfc + bfc directly.

template <bool FUSE_FC>
__global__ void __launch_bounds__(256)
k_pull(const float* __restrict__ bias, const float* __restrict__ Wfc,
       const float* __restrict__ bfc, float* __restrict__ out) {
    int lane = threadIdx.x & 31;
    int row = blockIdx.x * 8 + (threadIdx.x >> 5);
    if (row >= N_NODES) return;

    float di = g_dinv[row];
    float c = di * di;
    const float* hr = &g_hA[(size_t)row * HID];
    float a0 = fmaf(hr[lane],      c, bias[lane]);
    float a1 = fmaf(hr[lane + 32], c, bias[lane + 32]);

    int start = g_rowptr[row];
    int end   = g_rowptr[row + 1];
    for (int i = start; i < end; i += 32) {
        int n = min(32, end - i);
        int2 pk = make_int2(0, 0);
        if (i + lane < end) pk = g_epack[i + lane];
        for (int j = 0; j < n; j++) {
            int   s  = __shfl_sync(~0u, pk.x, j);
            float nm = __int_as_float(__shfl_sync(~0u, pk.y, j));
            const float* hs = &g_hA[(size_t)s * HID];
            a0 = fmaf(hs[lane],      nm, a0);
            a1 = fmaf(hs[lane + 32], nm, a1);
        }
    }

    if (!FUSE_FC) {
        g_hB[(size_t)row * HID + lane]      = a0;
        g_hB[(size_t)row * HID + lane + 32] = a1;
    } else {
        a0 = fmaxf(a0, 0.f);
        a1 = fmaxf(a1, 0.f);
        float res[OUT_DIM];
#pragma unroll
        for (int k = 0; k < OUT_DIM; k++) {
            float p = a0 * __ldg(&Wfc[lane * OUT_DIM + k]) +
                      a1 * __ldg(&Wfc[(lane + 32) * OUT_DIM + k]);
#pragma unroll
            for (int o = 16; o > 0; o >>= 1) p += __shfl_xor_sync(~0u, p, o);
            res[k] = p;
        }
        if (lane < OUT_DIM)
            out[(size_t)row * OUT_DIM + lane] = res[lane] + bfc[lane];
    }
}

// ---------------- launcher: kernel launches ONLY ----------------

extern "C" void kernel_launch(void* const* d_in, const int* in_sizes, int n_in,
                              void* d_out, int out_size) {
    const float* x   = (const float*)d_in[0];
    const int*   ei  = (const int*)d_in[1];    // int32 (JAX x64 disabled)
    const float* ew  = (const float*)d_in[2];
    const float* W1  = (const float*)d_in[3];
    const float* b1  = (const float*)d_in[4];
    const float* W2  = (const float*)d_in[5];
    const float* b2  = (const float*)d_in[6];
    const float* Wfc = (const float*)d_in[7];
    const float* bfc = (const float*)d_in[8];
    float* out = (float*)d_out;

    const int T = 256;
    int gbN    = (N_NODES + T - 1) / T;
    int gbE    = (N_EDGES + T - 1) / T;
    int gbGemm = (N_NODES + 127) / 128;
    int gbPull = (N_NODES + 7) / 8;

    // degree + CSR build (shared by both layers)
    k_init<<<gbN, T>>>();
    k_accum_deg<<<gbE, T>>>(ei, ew);
    k_rsqrt<<<gbN, T>>>();
    k_scan1<<<NBLK, SB>>>();
    k_scan2<<<1, 32>>>();
    k_scan3<<<NBLK, SB>>>();
    k_fill<<<gbE, T>>>(ei, ew);

    // layer 1
    k_gemm64<false, false><<<gbGemm, T>>>(x, W1, IN_DIM);
    k_pull<false><<<gbPull, T>>>(b1, nullptr, nullptr, nullptr);

    // layer 2 + fused FC
    k_gemm64<true, true><<<gbGemm, T>>>(nullptr, W2, HID);
    k_pull<true><<<gbPull, T>>>(b2, Wfc, bfc, out);
}

// round 8
// speedup vs baseline: 1.7293x; 1.0618x over previous
#include <cuda_runtime.h>
#include <cstdint>

#define N_NODES 100000
#define N_EDGES 3200000
#define IN_DIM  512
#define HID     64
#define OUT_DIM 5

#define SB 1024
#define NBLK ((N_NODES + SB - 1) / SB)   // 98

// Scratch (allocation-free rule): __device__ globals, device-code refs only.
__device__ __align__(16) float g_dinv[N_NODES];
__device__ __align__(16) float g_hA[(size_t)N_NODES * HID];
__device__ __align__(16) float g_hB[(size_t)N_NODES * HID];
// CSR (dst-binned), rebuilt each launch, shared by both layers.
__device__ int  g_cnt[N_NODES];
__device__ int  g_rowptr[N_NODES + 1];
__device__ int  g_cursor[N_NODES];
__device__ int  g_bsum[NBLK];
__device__ __align__(8) int2 g_epack[N_EDGES];   // {src, bitcast(norm)}

// ---------------- degree + incoming-count ----------------

__global__ void k_init() {
    int i = blockIdx.x * blockDim.x + threadIdx.x;
    if (i < N_NODES) { g_dinv[i] = 1.0f; g_cnt[i] = 0; }
}

__global__ void k_accum_deg(const int* __restrict__ ei,
                            const float* __restrict__ ew) {
    int e = blockIdx.x * blockDim.x + threadIdx.x;
    if (e < N_EDGES) {
        int d = ei[N_EDGES + e];
        atomicAdd(&g_dinv[d], ew[e]);
        atomicAdd(&g_cnt[d], 1);
    }
}

__global__ void k_rsqrt() {
    int i = blockIdx.x * blockDim.x + threadIdx.x;
    if (i < N_NODES) g_dinv[i] = rsqrtf(g_dinv[i]);
}

// ---------------- multi-block 3-phase prefix scan ----------------

__global__ void __launch_bounds__(SB) k_scan1() {
    __shared__ int ws[32];
    int tid = threadIdx.x, lane = tid & 31, wid = tid >> 5;
    int i = blockIdx.x * SB + tid;
    int v = (i < N_NODES) ? g_cnt[i] : 0;
    int x = v;
#pragma unroll
    for (int o = 1; o < 32; o <<= 1) {
        int y = __shfl_up_sync(~0u, x, o);
        if (lane >= o) x += y;
    }
    if (lane == 31) ws[wid] = x;
    __syncthreads();
    if (wid == 0) {
        int w = ws[lane];
#pragma unroll
        for (int o = 1; o < 32; o <<= 1) {
            int y = __shfl_up_sync(~0u, w, o);
            if (lane >= o) w += y;
        }
        ws[lane] = w;
    }
    __syncthreads();
    int incl = x + (wid > 0 ? ws[wid - 1] : 0);
    if (i < N_NODES) g_rowptr[i + 1] = incl;
    if (tid == SB - 1) g_bsum[blockIdx.x] = incl;
}

__global__ void k_scan2() {
    int lane = threadIdx.x;
    int carry = 0;
    for (int base = 0; base < NBLK; base += 32) {
        int v = (base + lane < NBLK) ? g_bsum[base + lane] : 0;
        int x = v;
#pragma unroll
        for (int o = 1; o < 32; o <<= 1) {
            int y = __shfl_up_sync(~0u, x, o);
            if (lane >= o) x += y;
        }
        if (base + lane < NBLK) g_bsum[base + lane] = x - v + carry;
        carry += __shfl_sync(~0u, x, 31);
    }
}

__global__ void __launch_bounds__(SB) k_scan3() {
    int i = blockIdx.x * SB + threadIdx.x;
    if (i >= N_NODES) return;
    int off = g_bsum[i >> 10];
    int r = g_rowptr[i + 1] + off;
    g_rowptr[i + 1] = r;
    g_cursor[i] = r - g_cnt[i];
    if (i == 0) g_rowptr[0] = 0;
}

// ---------------- CSR fill ----------------

__global__ void k_fill(const int* __restrict__ ei, const float* __restrict__ ew) {
    int e = blockIdx.x * blockDim.x + threadIdx.x;
    if (e >= N_EDGES) return;
    int s = ei[e];
    int d = ei[N_EDGES + e];
    float nm = g_dinv[s] * ew[e] * g_dinv[d];
    int pos = atomicAdd(&g_cursor[d], 1);
    g_epack[pos] = make_int2(s, __float_as_int(nm));
}

// ---------------- tf32 helpers ----------------

__device__ __forceinline__ uint32_t f2tf(float v) {
    uint32_t r;
    asm("cvt.rna.tf32.f32 %0, %1;" : "=r"(r) : "f"(v));
    return r;
}

__device__ __forceinline__ void mma_tf32(float* c, const uint32_t* a, const uint32_t* b) {
    asm volatile(
        "mma.sync.aligned.m16n8k8.row.col.f32.tf32.tf32.f32 "
        "{%0,%1,%2,%3}, {%4,%5,%6,%7}, {%8,%9}, {%0,%1,%2,%3};"
        : "+f"(c[0]), "+f"(c[1]), "+f"(c[2]), "+f"(c[3])
        : "r"(a[0]), "r"(a[1]), "r"(a[2]), "r"(a[3]), "r"(b[0]), "r"(b[1]));
}

// ------- 3xTF32 tensor-core GEMM (layer 1): g_hA = x @ W1, K=512 -------
// Block 128x64, 8 warps in 4(m) x 2(n) grid, warp tile 32x32, BK=16.

#define APITCH 20   // 16 + 4 pad: conflict-free frag loads, 80B rows (16B-aligned)
#define BPITCH 72   // 64 + 8 pad: conflict-free frag loads, 288B rows

__global__ void __launch_bounds__(256)
k_gemm_tf32(const float* __restrict__ A, const float* __restrict__ B, int K) {
    __shared__ uint32_t Ahi[128 * APITCH], Alo[128 * APITCH];
    __shared__ uint32_t Bhi[16 * BPITCH],  Blo[16 * BPITCH];

    const int M = N_NODES;
    int tid  = threadIdx.x;
    int wid  = tid >> 5;
    int lane = tid & 31;
    int wm = wid >> 1, wn = wid & 1;       // 4x2 warp grid
    int qr = lane >> 2, qc = lane & 3;
    int rowBase = blockIdx.x * 128;

    // global-load coords (A: 2 float4/thread, B: 1 float4/thread per iter)
    int ar0 = tid >> 2,        ac0 = (tid & 3) * 4;       // rows 0..63
    int ar1 = (tid >> 2) + 64, ac1 = ac0;                 // rows 64..127
    int brr = tid >> 4,        bcc = (tid & 15) * 4;      // B 16x64

    float acc[2][4][4];
#pragma unroll
    for (int mt = 0; mt < 2; mt++)
#pragma unroll
        for (int nt = 0; nt < 4; nt++)
#pragma unroll
            for (int i = 0; i < 4; i++) acc[mt][nt][i] = 0.0f;

    float4 pa0, pa1, pb;
    auto loadG = [&](int k0) {
        int g0 = rowBase + ar0, g1 = rowBase + ar1;
        pa0 = make_float4(0.f, 0.f, 0.f, 0.f);
        pa1 = make_float4(0.f, 0.f, 0.f, 0.f);
        if (g0 < M) pa0 = *reinterpret_cast<const float4*>(&A[(size_t)g0 * K + k0 + ac0]);
        if (g1 < M) pa1 = *reinterpret_cast<const float4*>(&A[(size_t)g1 * K + k0 + ac1]);
        pb = *reinterpret_cast<const float4*>(&B[(size_t)(k0 + brr) * HID + bcc]);
    };
    auto split4 = [&](float4 v, uint32_t* h, uint32_t* l) {
        float f[4] = {v.x, v.y, v.z, v.w};
#pragma unroll
        for (int i = 0; i < 4; i++) {
            h[i] = f2tf(f[i]);
            l[i] = f2tf(f[i] - __uint_as_float(h[i]));
        }
    };
    auto commit = [&]() {
        uint32_t h[4], l[4];
        split4(pa0, h, l);
#pragma unroll
        for (int i = 0; i < 4; i++) { Ahi[ar0 * APITCH + ac0 + i] = h[i]; Alo[ar0 * APITCH + ac0 + i] = l[i]; }
        split4(pa1, h, l);
#pragma unroll
        for (int i = 0; i < 4; i++) { Ahi[ar1 * APITCH + ac1 + i] = h[i]; Alo[ar1 * APITCH + ac1 + i] = l[i]; }
        split4(pb, h, l);
#pragma unroll
        for (int i = 0; i < 4; i++) { Bhi[brr * BPITCH + bcc + i] = h[i]; Blo[brr * BPITCH + bcc + i] = l[i]; }
    };

    loadG(0);
    for (int k0 = 0; k0 < K; k0 += 16) {
        commit();
        __syncthreads();
        if (k0 + 16 < K) loadG(k0 + 16);

#pragma unroll
        for (int ks = 0; ks < 16; ks += 8) {
            // load fragments
            uint32_t fah[2][4], fal[2][4];
#pragma unroll
            for (int mt = 0; mt < 2; mt++) {
                int r0 = wm * 32 + mt * 16 + qr;
                int c0 = ks + qc;
                fah[mt][0] = Ahi[r0 * APITCH + c0];
                fah[mt][1] = Ahi[(r0 + 8) * APITCH + c0];
                fah[mt][2] = Ahi[r0 * APITCH + c0 + 4];
                fah[mt][3] = Ahi[(r0 + 8) * APITCH + c0 + 4];
                fal[mt][0] = Alo[r0 * APITCH + c0];
                fal[mt][1] = Alo[(r0 + 8) * APITCH + c0];
                fal[mt][2] = Alo[r0 * APITCH + c0 + 4];
                fal[mt][3] = Alo[(r0 + 8) * APITCH + c0 + 4];
            }
            uint32_t fbh[4][2], fbl[4][2];
#pragma unroll
            for (int nt = 0; nt < 4; nt++) {
                int col = wn * 32 + nt * 8 + qr;
                int kk = ks + qc;
                fbh[nt][0] = Bhi[kk * BPITCH + col];
                fbh[nt][1] = Bhi[(kk + 4) * BPITCH + col];
                fbl[nt][0] = Blo[kk * BPITCH + col];
                fbl[nt][1] = Blo[(kk + 4) * BPITCH + col];
            }
#pragma unroll
            for (int mt = 0; mt < 2; mt++)
#pragma unroll
                for (int nt = 0; nt < 4; nt++) {
                    mma_tf32(acc[mt][nt], fah[mt], fbh[nt]);   // hi*hi
                    mma_tf32(acc[mt][nt], fah[mt], fbl[nt]);   // hi*lo
                    mma_tf32(acc[mt][nt], fal[mt], fbh[nt]);   // lo*hi
                }
        }
        __syncthreads();
    }

    // epilogue: c0 (r, 2qc), c1 (r, 2qc+1), c2 (r+8, 2qc), c3 (r+8, 2qc+1)
#pragma unroll
    for (int mt = 0; mt < 2; mt++) {
#pragma unroll
        for (int nt = 0; nt < 4; nt++) {
            int r  = rowBase + wm * 32 + mt * 16 + qr;
            int cc = wn * 32 + nt * 8 + qc * 2;
            if (r < M)
                *reinterpret_cast<float2*>(&g_hA[(size_t)r * HID + cc]) =
                    make_float2(acc[mt][nt][0], acc[mt][nt][1]);
            if (r + 8 < M)
                *reinterpret_cast<float2*>(&g_hA[(size_t)(r + 8) * HID + cc]) =
                    make_float2(acc[mt][nt][2], acc[mt][nt][3]);
        }
    }
}

// ------- FFMA GEMM (layer 2, K=64): g_hA = relu(g_hB) @ W2 -------

__global__ void __launch_bounds__(256)
k_gemm64(const float* __restrict__ B, int K) {
    const int BM = 128, BN = 64, BK = 32, TM = 8, TN = 4;
    __shared__ float As[BK][BM];
    __shared__ float Bs[BK][BN];

    const float* A = g_hB;
    const int M = N_NODES;

    int tid = threadIdx.x;
    int tx = tid & 15;
    int ty = tid >> 4;
    int rowBase = blockIdx.x * BM;

    float acc[TM][TN];
#pragma unroll
    for (int m = 0; m < TM; m++)
#pragma unroll
        for (int n = 0; n < TN; n++) acc[m][n] = 0.0f;

    for (int k0 = 0; k0 < K; k0 += BK) {
#pragma unroll
        for (int i = 0; i < 4; i++) {
            int idx = tid + i * 256;
            int r   = idx >> 3;
            int k4  = idx & 7;
            int grow = rowBase + r;
            float4 v = make_float4(0.f, 0.f, 0.f, 0.f);
            if (grow < M)
                v = *reinterpret_cast<const float4*>(&A[(size_t)grow * K + k0 + k4 * 4]);
            v.x = fmaxf(v.x, 0.f); v.y = fmaxf(v.y, 0.f);
            v.z = fmaxf(v.z, 0.f); v.w = fmaxf(v.w, 0.f);
            As[k4 * 4 + 0][r] = v.x;
            As[k4 * 4 + 1][r] = v.y;
            As[k4 * 4 + 2][r] = v.z;
            As[k4 * 4 + 3][r] = v.w;
        }
#pragma unroll
        for (int i = 0; i < 2; i++) {
            int idx = tid + i * 256;
            int r = idx >> 4;
            int c4 = idx & 15;
            *reinterpret_cast<float4*>(&Bs[r][c4 * 4]) =
                *reinterpret_cast<const float4*>(&B[(size_t)(k0 + r) * BN + c4 * 4]);
        }
        __syncthreads();

#pragma unroll
        for (int k = 0; k < BK; k++) {
            float a[TM], b[TN];
#pragma unroll
            for (int m = 0; m < TM; m++) a[m] = As[k][ty * TM + m];
#pragma unroll
            for (int n = 0; n < TN; n++) b[n] = Bs[k][tx * TN + n];
#pragma unroll
            for (int m = 0; m < TM; m++)
#pragma unroll
                for (int n = 0; n < TN; n++) acc[m][n] = fmaf(a[m], b[n], acc[m][n]);
        }
        __syncthreads();
    }

#pragma unroll
    for (int m = 0; m < TM; m++) {
        int grow = rowBase + ty * TM + m;
        if (grow < M) {
            float4 v = make_float4(acc[m][0], acc[m][1], acc[m][2], acc[m][3]);
            *reinterpret_cast<float4*>(&g_hA[(size_t)grow * BN + tx * TN]) = v;
        }
    }
}

// -------- pull aggregation: one warp per dst row --------

template <bool FUSE_FC>
__global__ void __launch_bounds__(256)
k_pull(const float* __restrict__ bias, const float* __restrict__ Wfc,
       const float* __restrict__ bfc, float* __restrict__ out) {
    int lane = threadIdx.x & 31;
    int row = blockIdx.x * 8 + (threadIdx.x >> 5);
    if (row >= N_NODES) return;

    float di = g_dinv[row];
    float c = di * di;
    const float* hr = &g_hA[(size_t)row * HID];
    float a0 = fmaf(hr[lane],      c, bias[lane]);
    float a1 = fmaf(hr[lane + 32], c, bias[lane + 32]);

    int start = g_rowptr[row];
    int end   = g_rowptr[row + 1];
    for (int i = start; i < end; i += 32) {
        int n = min(32, end - i);
        int2 pk = make_int2(0, 0);
        if (i + lane < end) pk = g_epack[i + lane];
        for (int j = 0; j < n; j++) {
            int   s  = __shfl_sync(~0u, pk.x, j);
            float nm = __int_as_float(__shfl_sync(~0u, pk.y, j));
            const float* hs = &g_hA[(size_t)s * HID];
            a0 = fmaf(hs[lane],      nm, a0);
            a1 = fmaf(hs[lane + 32], nm, a1);
        }
    }

    if (!FUSE_FC) {
        g_hB[(size_t)row * HID + lane]      = a0;
        g_hB[(size_t)row * HID + lane + 32] = a1;
    } else {
        a0 = fmaxf(a0, 0.f);
        a1 = fmaxf(a1, 0.f);
        float res[OUT_DIM];
#pragma unroll
        for (int k = 0; k < OUT_DIM; k++) {
            float p = a0 * __ldg(&Wfc[lane * OUT_DIM + k]) +
                      a1 * __ldg(&Wfc[(lane + 32) * OUT_DIM + k]);
#pragma unroll
            for (int o = 16; o > 0; o >>= 1) p += __shfl_xor_sync(~0u, p, o);
            res[k] = p;
        }
        if (lane < OUT_DIM)
            out[(size_t)row * OUT_DIM + lane] = res[lane] + bfc[lane];
    }
}

// ---------------- launcher ----------------

extern "C" void kernel_launch(void* const* d_in, const int* in_sizes, int n_in,
                              void* d_out, int out_size) {
    const float* x   = (const float*)d_in[0];
    const int*   ei  = (const int*)d_in[1];    // int32 (JAX x64 disabled)
    const float* ew  = (const float*)d_in[2];
    const float* W1  = (const float*)d_in[3];
    const float* b1  = (const float*)d_in[4];
    const float* W2  = (const float*)d_in[5];
    const float* b2  = (const float*)d_in[6];
    const float* Wfc = (const float*)d_in[7];
    const float* bfc = (const float*)d_in[8];
    float* out = (float*)d_out;

    const int T = 256;
    int gbN    = (N_NODES + T - 1) / T;
    int gbE    = (N_EDGES + T - 1) / T;
    int gbGemm = (N_NODES + 127) / 128;
    int gbPull = (N_NODES + 7) / 8;

    // degree + CSR build (shared by both layers)
    k_init<<<gbN, T>>>();
    k_accum_deg<<<gbE, T>>>(ei, ew);
    k_rsqrt<<<gbN, T>>>();
    k_scan1<<<NBLK, SB>>>();
    k_scan2<<<1, 32>>>();
    k_scan3<<<NBLK, SB>>>();
    k_fill<<<gbE, T>>>(ei, ew);

    // layer 1: tensor-core 3xTF32 GEMM
    k_gemm_tf32<<<gbGemm, T>>>(x, W1, IN_DIM);
    k_pull<false><<<gbPull, T>>>(b1, nullptr, nullptr, nullptr);

    // layer 2 + fused FC
    k_gemm64<<<gbGemm, T>>>(W2, HID);
    k_pull<true><<<gbPull, T>>>(b2, Wfc, bfc, out);
}

// round 9
// speedup vs baseline: 1.9566x; 1.1315x over previous
#include <cuda_runtime.h>
#include <cstdint>

#define N_NODES 100000
#define N_EDGES 3200000
#define IN_DIM  512
#define HID     64
#define OUT_DIM 5

#define SB 1024
#define NBLK ((N_NODES + SB - 1) / SB)   // 98

// Scratch (allocation-free rule): __device__ globals, device-code refs only.
__device__ __align__(16) float g_dinv[N_NODES];
__device__ __align__(16) float g_hA[(size_t)N_NODES * HID];
__device__ __align__(16) float g_hB[(size_t)N_NODES * HID];
// CSR (dst-binned), rebuilt each launch, shared by both layers.
__device__ int  g_cnt[N_NODES];
__device__ int  g_rowptr[N_NODES + 1];
__device__ int  g_cursor[N_NODES];
__device__ int  g_bsum[NBLK];
__device__ __align__(8) int2 g_epack[N_EDGES];   // {src, bitcast(norm)}

// ---------------- degree + incoming-count ----------------

__global__ void k_init() {
    int i = blockIdx.x * blockDim.x + threadIdx.x;
    if (i < N_NODES) { g_dinv[i] = 1.0f; g_cnt[i] = 0; }
}

__global__ void k_accum_deg(const int* __restrict__ ei,
                            const float* __restrict__ ew) {
    int e = blockIdx.x * blockDim.x + threadIdx.x;
    if (e < N_EDGES) {
        int d = ei[N_EDGES + e];
        atomicAdd(&g_dinv[d], ew[e]);
        atomicAdd(&g_cnt[d], 1);
    }
}

__global__ void k_rsqrt() {
    int i = blockIdx.x * blockDim.x + threadIdx.x;
    if (i < N_NODES) g_dinv[i] = rsqrtf(g_dinv[i]);
}

// ---------------- multi-block 3-phase prefix scan ----------------

__global__ void __launch_bounds__(SB) k_scan1() {
    __shared__ int ws[32];
    int tid = threadIdx.x, lane = tid & 31, wid = tid >> 5;
    int i = blockIdx.x * SB + tid;
    int v = (i < N_NODES) ? g_cnt[i] : 0;
    int x = v;
#pragma unroll
    for (int o = 1; o < 32; o <<= 1) {
        int y = __shfl_up_sync(~0u, x, o);
        if (lane >= o) x += y;
    }
    if (lane == 31) ws[wid] = x;
    __syncthreads();
    if (wid == 0) {
        int w = ws[lane];
#pragma unroll
        for (int o = 1; o < 32; o <<= 1) {
            int y = __shfl_up_sync(~0u, w, o);
            if (lane >= o) w += y;
        }
        ws[lane] = w;
    }
    __syncthreads();
    int incl = x + (wid > 0 ? ws[wid - 1] : 0);
    if (i < N_NODES) g_rowptr[i + 1] = incl;
    if (tid == SB - 1) g_bsum[blockIdx.x] = incl;
}

__global__ void k_scan2() {
    int lane = threadIdx.x;
    int carry = 0;
    for (int base = 0; base < NBLK; base += 32) {
        int v = (base + lane < NBLK) ? g_bsum[base + lane] : 0;
        int x = v;
#pragma unroll
        for (int o = 1; o < 32; o <<= 1) {
            int y = __shfl_up_sync(~0u, x, o);
            if (lane >= o) x += y;
        }
        if (base + lane < NBLK) g_bsum[base + lane] = x - v + carry;
        carry += __shfl_sync(~0u, x, 31);
    }
}

__global__ void __launch_bounds__(SB) k_scan3() {
    int i = blockIdx.x * SB + threadIdx.x;
    if (i >= N_NODES) return;
    int off = g_bsum[i >> 10];
    int r = g_rowptr[i + 1] + off;
    g_rowptr[i + 1] = r;
    g_cursor[i] = r - g_cnt[i];
    if (i == 0) g_rowptr[0] = 0;
}

// ---------------- CSR fill ----------------

__global__ void k_fill(const int* __restrict__ ei, const float* __restrict__ ew) {
    int e = blockIdx.x * blockDim.x + threadIdx.x;
    if (e >= N_EDGES) return;
    int s = ei[e];
    int d = ei[N_EDGES + e];
    float nm = g_dinv[s] * ew[e] * g_dinv[d];
    int pos = atomicAdd(&g_cursor[d], 1);
    g_epack[pos] = make_int2(s, __float_as_int(nm));
}

// ---------------- tf32 helpers ----------------

__device__ __forceinline__ uint32_t f2tf(float v) {
    uint32_t r;
    asm("cvt.rna.tf32.f32 %0, %1;" : "=r"(r) : "f"(v));
    return r;
}

__device__ __forceinline__ void split_tf(float v, uint32_t& h, uint32_t& l) {
    h = f2tf(v);
    l = f2tf(v - __uint_as_float(h));
}

__device__ __forceinline__ void mma_tf32(float* c, const uint32_t* a, const uint32_t* b) {
    asm volatile(
        "mma.sync.aligned.m16n8k8.row.col.f32.tf32.tf32.f32 "
        "{%0,%1,%2,%3}, {%4,%5,%6,%7}, {%8,%9}, {%0,%1,%2,%3};"
        : "+f"(c[0]), "+f"(c[1]), "+f"(c[2]), "+f"(c[3])
        : "r"(a[0]), "r"(a[1]), "r"(a[2]), "r"(a[3]), "r"(b[0]), "r"(b[1]));
}

__device__ __forceinline__ void cp16(uint32_t dst, const void* src, bool valid) {
    asm volatile("cp.async.cg.shared.global [%0], [%1], 16, %2;"
                 :: "r"(dst), "l"(src), "r"(valid ? 16 : 0) : "memory");
}

// ------- 3xTF32 tensor-core GEMM (layer 1): g_hA = x @ W1, K=512 -------
// Block 128x64, 8 warps 4(m)x2(n), warp tile 32x32, BK=16.
// cp.async double-buffered raw-f32 tiles; hi/lo split at fragment load.

#define APITCH 20   // 16+4 pad; 80B rows (16B-aligned), conflict-free frags
#define BPITCH 72   // 64+8 pad; 288B rows, conflict-free frags

__global__ void __launch_bounds__(256)
k_gemm_tf32(const float* __restrict__ A, const float* __restrict__ B, int K) {
    __shared__ float As[2][128 * APITCH];
    __shared__ float Bs[2][16 * BPITCH];

    const int M = N_NODES;
    int tid  = threadIdx.x;
    int wid  = tid >> 5;
    int lane = tid & 31;
    int wm = wid >> 1, wn = wid & 1;
    int qr = lane >> 2, qc = lane & 3;
    int rowBase = blockIdx.x * 128;

    // load coords: A 128x16 = 512 float4s (2/thread), B 16x64 = 256 (1/thread)
    int ar0 = tid >> 2,         ac0 = (tid & 3) * 4;
    int ar1 = (tid >> 2) + 64,  ac1 = ac0;
    int brr = tid >> 4,         bcc = (tid & 15) * 4;

    uint32_t sA0[2], sA1[2], sB0[2];
#pragma unroll
    for (int b = 0; b < 2; b++) {
        sA0[b] = (uint32_t)__cvta_generic_to_shared(&As[b][ar0 * APITCH + ac0]);
        sA1[b] = (uint32_t)__cvta_generic_to_shared(&As[b][ar1 * APITCH + ac1]);
        sB0[b] = (uint32_t)__cvta_generic_to_shared(&Bs[b][brr * BPITCH + bcc]);
    }

    auto loadTiles = [&](int k0, int buf) {
        int g0 = rowBase + ar0, g1 = rowBase + ar1;
        bool v0 = g0 < M, v1 = g1 < M;
        cp16(sA0[buf], &A[(size_t)(v0 ? g0 : 0) * K + k0 + ac0], v0);
        cp16(sA1[buf], &A[(size_t)(v1 ? g1 : 0) * K + k0 + ac1], v1);
        cp16(sB0[buf], &B[(size_t)(k0 + brr) * HID + bcc], true);
        asm volatile("cp.async.commit_group;" ::: "memory");
    };

    float acc[2][4][4];
#pragma unroll
    for (int mt = 0; mt < 2; mt++)
#pragma unroll
        for (int nt = 0; nt < 4; nt++)
#pragma unroll
            for (int i = 0; i < 4; i++) acc[mt][nt][i] = 0.0f;

    const int NIT = K / 16;   // 32
    loadTiles(0, 0);

    for (int it = 0; it < NIT; it++) {
        int buf = it & 1;
        if (it + 1 < NIT) {
            loadTiles((it + 1) * 16, buf ^ 1);
            asm volatile("cp.async.wait_group 1;" ::: "memory");
        } else {
            asm volatile("cp.async.wait_group 0;" ::: "memory");
        }
        __syncthreads();

        const float* as = As[buf];
        const float* bs = Bs[buf];
#pragma unroll
        for (int ks = 0; ks < 16; ks += 8) {
            uint32_t fah[2][4], fal[2][4];
#pragma unroll
            for (int mt = 0; mt < 2; mt++) {
                int r0 = wm * 32 + mt * 16 + qr;
                int c0 = ks + qc;
                split_tf(as[r0 * APITCH + c0],           fah[mt][0], fal[mt][0]);
                split_tf(as[(r0 + 8) * APITCH + c0],     fah[mt][1], fal[mt][1]);
                split_tf(as[r0 * APITCH + c0 + 4],       fah[mt][2], fal[mt][2]);
                split_tf(as[(r0 + 8) * APITCH + c0 + 4], fah[mt][3], fal[mt][3]);
            }
            uint32_t fbh[4][2], fbl[4][2];
#pragma unroll
            for (int nt = 0; nt < 4; nt++) {
                int col = wn * 32 + nt * 8 + qr;
                int kk = ks + qc;
                split_tf(bs[kk * BPITCH + col],       fbh[nt][0], fbl[nt][0]);
                split_tf(bs[(kk + 4) * BPITCH + col], fbh[nt][1], fbl[nt][1]);
            }
#pragma unroll
            for (int mt = 0; mt < 2; mt++)
#pragma unroll
                for (int nt = 0; nt < 4; nt++) {
                    mma_tf32(acc[mt][nt], fah[mt], fbh[nt]);   // hi*hi
                    mma_tf32(acc[mt][nt], fah[mt], fbl[nt]);   // hi*lo
                    mma_tf32(acc[mt][nt], fal[mt], fbh[nt]);   // lo*hi
                }
        }
        __syncthreads();
    }

    // epilogue: c0 (r, 2qc), c1 (r, 2qc+1), c2 (r+8, 2qc), c3 (r+8, 2qc+1)
#pragma unroll
    for (int mt = 0; mt < 2; mt++) {
#pragma unroll
        for (int nt = 0; nt < 4; nt++) {
            int r  = rowBase + wm * 32 + mt * 16 + qr;
            int cc = wn * 32 + nt * 8 + qc * 2;
            if (r < M)
                *reinterpret_cast<float2*>(&g_hA[(size_t)r * HID + cc]) =
                    make_float2(acc[mt][nt][0], acc[mt][nt][1]);
            if (r + 8 < M)
                *reinterpret_cast<float2*>(&g_hA[(size_t)(r + 8) * HID + cc]) =
                    make_float2(acc[mt][nt][2], acc[mt][nt][3]);
        }
    }
}

// ------- FFMA GEMM (layer 2, K=64): g_hA = relu(g_hB) @ W2 -------

__global__ void __launch_bounds__(256)
k_gemm64(const float* __restrict__ B, int K) {
    const int BM = 128, BN = 64, BK = 32, TM = 8, TN = 4;
    __shared__ float As[BK][BM];
    __shared__ float Bs[BK][BN];

    const float* A = g_hB;
    const int M = N_NODES;

    int tid = threadIdx.x;
    int tx = tid & 15;
    int ty = tid >> 4;
    int rowBase = blockIdx.x * BM;

    float acc[TM][TN];
#pragma unroll
    for (int m = 0; m < TM; m++)
#pragma unroll
        for (int n = 0; n < TN; n++) acc[m][n] = 0.0f;

    for (int k0 = 0; k0 < K; k0 += BK) {
#pragma unroll
        for (int i = 0; i < 4; i++) {
            int idx = tid + i * 256;
            int r   = idx >> 3;
            int k4  = idx & 7;
            int grow = rowBase + r;
            float4 v = make_float4(0.f, 0.f, 0.f, 0.f);
            if (grow < M)
                v = *reinterpret_cast<const float4*>(&A[(size_t)grow * K + k0 + k4 * 4]);
            v.x = fmaxf(v.x, 0.f); v.y = fmaxf(v.y, 0.f);
            v.z = fmaxf(v.z, 0.f); v.w = fmaxf(v.w, 0.f);
            As[k4 * 4 + 0][r] = v.x;
            As[k4 * 4 + 1][r] = v.y;
            As[k4 * 4 + 2][r] = v.z;
            As[k4 * 4 + 3][r] = v.w;
        }
#pragma unroll
        for (int i = 0; i < 2; i++) {
            int idx = tid + i * 256;
            int r = idx >> 4;
            int c4 = idx & 15;
            *reinterpret_cast<float4*>(&Bs[r][c4 * 4]) =
                *reinterpret_cast<const float4*>(&B[(size_t)(k0 + r) * BN + c4 * 4]);
        }
        __syncthreads();

#pragma unroll
        for (int k = 0; k < BK; k++) {
            float a[TM], b[TN];
#pragma unroll
            for (int m = 0; m < TM; m++) a[m] = As[k][ty * TM + m];
#pragma unroll
            for (int n = 0; n < TN; n++) b[n] = Bs[k][tx * TN + n];
#pragma unroll
            for (int m = 0; m < TM; m++)
#pragma unroll
                for (int n = 0; n < TN; n++) acc[m][n] = fmaf(a[m], b[n], acc[m][n]);
        }
        __syncthreads();
    }

#pragma unroll
    for (int m = 0; m < TM; m++) {
        int grow = rowBase + ty * TM + m;
        if (grow < M) {
            float4 v = make_float4(acc[m][0], acc[m][1], acc[m][2], acc[m][3]);
            *reinterpret_cast<float4*>(&g_hA[(size_t)grow * BN + tx * TN]) = v;
        }
    }
}

// -------- pull aggregation: one warp per dst row --------

template <bool FUSE_FC>
__global__ void __launch_bounds__(256)
k_pull(const float* __restrict__ bias, const float* __restrict__ Wfc,
       const float* __restrict__ bfc, float* __restrict__ out) {
    int lane = threadIdx.x & 31;
    int row = blockIdx.x * 8 + (threadIdx.x >> 5);
    if (row >= N_NODES) return;

    float di = g_dinv[row];
    float c = di * di;
    const float* hr = &g_hA[(size_t)row * HID];
    float a0 = fmaf(hr[lane],      c, bias[lane]);
    float a1 = fmaf(hr[lane + 32], c, bias[lane + 32]);

    int start = g_rowptr[row];
    int end   = g_rowptr[row + 1];
    for (int i = start; i < end; i += 32) {
        int n = min(32, end - i);
        int2 pk = make_int2(0, 0);
        if (i + lane < end) pk = g_epack[i + lane];
        for (int j = 0; j < n; j++) {
            int   s  = __shfl_sync(~0u, pk.x, j);
            float nm = __int_as_float(__shfl_sync(~0u, pk.y, j));
            const float* hs = &g_hA[(size_t)s * HID];
            a0 = fmaf(hs[lane],      nm, a0);
            a1 = fmaf(hs[lane + 32], nm, a1);
        }
    }

    if (!FUSE_FC) {
        g_hB[(size_t)row * HID + lane]      = a0;
        g_hB[(size_t)row * HID + lane + 32] = a1;
    } else {
        a0 = fmaxf(a0, 0.f);
        a1 = fmaxf(a1, 0.f);
        float res[OUT_DIM];
#pragma unroll
        for (int k = 0; k < OUT_DIM; k++) {
            float p = a0 * __ldg(&Wfc[lane * OUT_DIM + k]) +
                      a1 * __ldg(&Wfc[(lane + 32) * OUT_DIM + k]);
#pragma unroll
            for (int o = 16; o > 0; o >>= 1) p += __shfl_xor_sync(~0u, p, o);
            res[k] = p;
        }
        if (lane < OUT_DIM)
            out[(size_t)row * OUT_DIM + lane] = res[lane] + bfc[lane];
    }
}

// ---------------- launcher ----------------

extern "C" void kernel_launch(void* const* d_in, const int* in_sizes, int n_in,
                              void* d_out, int out_size) {
    const float* x   = (const float*)d_in[0];
    const int*   ei  = (const int*)d_in[1];    // int32 (JAX x64 disabled)
    const float* ew  = (const float*)d_in[2];
    const float* W1  = (const float*)d_in[3];
    const float* b1  = (const float*)d_in[4];
    const float* W2  = (const float*)d_in[5];
    const float* b2  = (const float*)d_in[6];
    const float* Wfc = (const float*)d_in[7];
    const float* bfc = (const float*)d_in[8];
    float* out = (float*)d_out;

    const int T = 256;
    int gbN    = (N_NODES + T - 1) / T;
    int gbE    = (N_EDGES + T - 1) / T;
    int gbGemm = (N_NODES + 127) / 128;
    int gbPull = (N_NODES + 7) / 8;

    // degree + CSR build (shared by both layers)
    k_init<<<gbN, T>>>();
    k_accum_deg<<<gbE, T>>>(ei, ew);
    k_rsqrt<<<gbN, T>>>();
    k_scan1<<<NBLK, SB>>>();
    k_scan2<<<1, 32>>>();
    k_scan3<<<NBLK, SB>>>();
    k_fill<<<gbE, T>>>(ei, ew);

    // layer 1: cp.async double-buffered 3xTF32 tensor-core GEMM
    k_gemm_tf32<<<gbGemm, T>>>(x, W1, IN_DIM);
    k_pull<false><<<gbPull, T>>>(b1, nullptr, nullptr, nullptr);

    // layer 2 + fused FC
    k_gemm64<<<gbGemm, T>>>(W2, HID);
    k_pull<true><<<gbPull, T>>>(b2, Wfc, bfc, out);
}

// round 10
// speedup vs baseline: 2.1988x; 1.1238x over previous
#include <cuda_runtime.h>
#include <cstdint>

#define N_NODES 100000
#define N_EDGES 3200000
#define IN_DIM  512
#define HID     64
#define OUT_DIM 5

#define SB 1024
#define NBLK ((N_NODES + SB - 1) / SB)   // 98

// Scratch (allocation-free rule): __device__ globals, device-code refs only.
__device__ __align__(16) float g_dinv[N_NODES];
__device__ __align__(16) float g_hA[(size_t)N_NODES * HID];
__device__ __align__(16) float g_hB[(size_t)N_NODES * HID];
// CSR (dst-binned), rebuilt each launch, shared by both layers.
__device__ int  g_cnt[N_NODES];
__device__ int  g_rowptr[N_NODES + 1];
__device__ int  g_cursor[N_NODES];
__device__ int  g_bsum[NBLK];
__device__ __align__(8) int2 g_epack[N_EDGES];   // {src, bitcast(norm)}

// ---------------- degree + incoming-count ----------------

__global__ void k_init() {
    int i = blockIdx.x * blockDim.x + threadIdx.x;
    if (i < N_NODES) { g_dinv[i] = 1.0f; g_cnt[i] = 0; }
}

__global__ void k_accum_deg(const int* __restrict__ ei,
                            const float* __restrict__ ew) {
    int e = blockIdx.x * blockDim.x + threadIdx.x;
    if (e < N_EDGES) {
        int d = ei[N_EDGES + e];
        atomicAdd(&g_dinv[d], ew[e]);
        atomicAdd(&g_cnt[d], 1);
    }
}

__global__ void k_rsqrt() {
    int i = blockIdx.x * blockDim.x + threadIdx.x;
    if (i < N_NODES) g_dinv[i] = rsqrtf(g_dinv[i]);
}

// ---------------- multi-block 3-phase prefix scan ----------------

__global__ void __launch_bounds__(SB) k_scan1() {
    __shared__ int ws[32];
    int tid = threadIdx.x, lane = tid & 31, wid = tid >> 5;
    int i = blockIdx.x * SB + tid;
    int v = (i < N_NODES) ? g_cnt[i] : 0;
    int x = v;
#pragma unroll
    for (int o = 1; o < 32; o <<= 1) {
        int y = __shfl_up_sync(~0u, x, o);
        if (lane >= o) x += y;
    }
    if (lane == 31) ws[wid] = x;
    __syncthreads();
    if (wid == 0) {
        int w = ws[lane];
#pragma unroll
        for (int o = 1; o < 32; o <<= 1) {
            int y = __shfl_up_sync(~0u, w, o);
            if (lane >= o) w += y;
        }
        ws[lane] = w;
    }
    __syncthreads();
    int incl = x + (wid > 0 ? ws[wid - 1] : 0);
    if (i < N_NODES) g_rowptr[i + 1] = incl;
    if (tid == SB - 1) g_bsum[blockIdx.x] = incl;
}

__global__ void k_scan2() {
    int lane = threadIdx.x;
    int carry = 0;
    for (int base = 0; base < NBLK; base += 32) {
        int v = (base + lane < NBLK) ? g_bsum[base + lane] : 0;
        int x = v;
#pragma unroll
        for (int o = 1; o < 32; o <<= 1) {
            int y = __shfl_up_sync(~0u, x, o);
            if (lane >= o) x += y;
        }
        if (base + lane < NBLK) g_bsum[base + lane] = x - v + carry;
        carry += __shfl_sync(~0u, x, 31);
    }
}

__global__ void __launch_bounds__(SB) k_scan3() {
    int i = blockIdx.x * SB + threadIdx.x;
    if (i >= N_NODES) return;
    int off = g_bsum[i >> 10];
    int r = g_rowptr[i + 1] + off;
    g_rowptr[i + 1] = r;
    g_cursor[i] = r - g_cnt[i];
    if (i == 0) g_rowptr[0] = 0;
}

// ---------------- CSR fill ----------------

__global__ void k_fill(const int* __restrict__ ei, const float* __restrict__ ew) {
    int e = blockIdx.x * blockDim.x + threadIdx.x;
    if (e >= N_EDGES) return;
    int s = ei[e];
    int d = ei[N_EDGES + e];
    float nm = g_dinv[s] * ew[e] * g_dinv[d];
    int pos = atomicAdd(&g_cursor[d], 1);
    g_epack[pos] = make_int2(s, __float_as_int(nm));
}

// ---------------- tf32 helpers ----------------

__device__ __forceinline__ uint32_t f2tf(float v) {
    uint32_t r;
    asm("cvt.rna.tf32.f32 %0, %1;" : "=r"(r) : "f"(v));
    return r;
}

__device__ __forceinline__ void split_tf(float v, uint32_t& h, uint32_t& l) {
    h = f2tf(v);
    l = f2tf(v - __uint_as_float(h));
}

__device__ __forceinline__ void mma_tf32(float* c, const uint32_t* a, const uint32_t* b) {
    asm volatile(
        "mma.sync.aligned.m16n8k8.row.col.f32.tf32.tf32.f32 "
        "{%0,%1,%2,%3}, {%4,%5,%6,%7}, {%8,%9}, {%0,%1,%2,%3};"
        : "+f"(c[0]), "+f"(c[1]), "+f"(c[2]), "+f"(c[3])
        : "r"(a[0]), "r"(a[1]), "r"(a[2]), "r"(a[3]), "r"(b[0]), "r"(b[1]));
}

__device__ __forceinline__ void cp16(uint32_t dst, const void* src, bool valid) {
    asm volatile("cp.async.cg.shared.global [%0], [%1], 16, %2;"
                 :: "r"(dst), "l"(src), "r"(valid ? 16 : 0) : "memory");
}

// ------- 3xTF32 tensor-core GEMM (layer 1): g_hA = x @ W1, K=512 -------

#define APITCH 20
#define BPITCH 72

__global__ void __launch_bounds__(256)
k_gemm_tf32(const float* __restrict__ A, const float* __restrict__ B, int K) {
    __shared__ float As[2][128 * APITCH];
    __shared__ float Bs[2][16 * BPITCH];

    const int M = N_NODES;
    int tid  = threadIdx.x;
    int wid  = tid >> 5;
    int lane = tid & 31;
    int wm = wid >> 1, wn = wid & 1;
    int qr = lane >> 2, qc = lane & 3;
    int rowBase = blockIdx.x * 128;

    int ar0 = tid >> 2,         ac0 = (tid & 3) * 4;
    int ar1 = (tid >> 2) + 64,  ac1 = ac0;
    int brr = tid >> 4,         bcc = (tid & 15) * 4;

    uint32_t sA0[2], sA1[2], sB0[2];
#pragma unroll
    for (int b = 0; b < 2; b++) {
        sA0[b] = (uint32_t)__cvta_generic_to_shared(&As[b][ar0 * APITCH + ac0]);
        sA1[b] = (uint32_t)__cvta_generic_to_shared(&As[b][ar1 * APITCH + ac1]);
        sB0[b] = (uint32_t)__cvta_generic_to_shared(&Bs[b][brr * BPITCH + bcc]);
    }

    auto loadTiles = [&](int k0, int buf) {
        int g0 = rowBase + ar0, g1 = rowBase + ar1;
        bool v0 = g0 < M, v1 = g1 < M;
        cp16(sA0[buf], &A[(size_t)(v0 ? g0 : 0) * K + k0 + ac0], v0);
        cp16(sA1[buf], &A[(size_t)(v1 ? g1 : 0) * K + k0 + ac1], v1);
        cp16(sB0[buf], &B[(size_t)(k0 + brr) * HID + bcc], true);
        asm volatile("cp.async.commit_group;" ::: "memory");
    };

    float acc[2][4][4];
#pragma unroll
    for (int mt = 0; mt < 2; mt++)
#pragma unroll
        for (int nt = 0; nt < 4; nt++)
#pragma unroll
            for (int i = 0; i < 4; i++) acc[mt][nt][i] = 0.0f;

    const int NIT = K / 16;
    loadTiles(0, 0);

    for (int it = 0; it < NIT; it++) {
        int buf = it & 1;
        if (it + 1 < NIT) {
            loadTiles((it + 1) * 16, buf ^ 1);
            asm volatile("cp.async.wait_group 1;" ::: "memory");
        } else {
            asm volatile("cp.async.wait_group 0;" ::: "memory");
        }
        __syncthreads();

        const float* as = As[buf];
        const float* bs = Bs[buf];
#pragma unroll
        for (int ks = 0; ks < 16; ks += 8) {
            uint32_t fah[2][4], fal[2][4];
#pragma unroll
            for (int mt = 0; mt < 2; mt++) {
                int r0 = wm * 32 + mt * 16 + qr;
                int c0 = ks + qc;
                split_tf(as[r0 * APITCH + c0],           fah[mt][0], fal[mt][0]);
                split_tf(as[(r0 + 8) * APITCH + c0],     fah[mt][1], fal[mt][1]);
                split_tf(as[r0 * APITCH + c0 + 4],       fah[mt][2], fal[mt][2]);
                split_tf(as[(r0 + 8) * APITCH + c0 + 4], fah[mt][3], fal[mt][3]);
            }
            uint32_t fbh[4][2], fbl[4][2];
#pragma unroll
            for (int nt = 0; nt < 4; nt++) {
                int col = wn * 32 + nt * 8 + qr;
                int kk = ks + qc;
                split_tf(bs[kk * BPITCH + col],       fbh[nt][0], fbl[nt][0]);
                split_tf(bs[(kk + 4) * BPITCH + col], fbh[nt][1], fbl[nt][1]);
            }
#pragma unroll
            for (int mt = 0; mt < 2; mt++)
#pragma unroll
                for (int nt = 0; nt < 4; nt++) {
                    mma_tf32(acc[mt][nt], fah[mt], fbh[nt]);
                    mma_tf32(acc[mt][nt], fah[mt], fbl[nt]);
                    mma_tf32(acc[mt][nt], fal[mt], fbh[nt]);
                }
        }
        __syncthreads();
    }

#pragma unroll
    for (int mt = 0; mt < 2; mt++) {
#pragma unroll
        for (int nt = 0; nt < 4; nt++) {
            int r  = rowBase + wm * 32 + mt * 16 + qr;
            int cc = wn * 32 + nt * 8 + qc * 2;
            if (r < M)
                *reinterpret_cast<float2*>(&g_hA[(size_t)r * HID + cc]) =
                    make_float2(acc[mt][nt][0], acc[mt][nt][1]);
            if (r + 8 < M)
                *reinterpret_cast<float2*>(&g_hA[(size_t)(r + 8) * HID + cc]) =
                    make_float2(acc[mt][nt][2], acc[mt][nt][3]);
        }
    }
}

// ------- FFMA GEMM (layer 2, K=64): g_hA = relu(g_hB) @ W2 -------

__global__ void __launch_bounds__(256)
k_gemm64(const float* __restrict__ B, int K) {
    const int BM = 128, BN = 64, BK = 32, TM = 8, TN = 4;
    __shared__ float As[BK][BM];
    __shared__ float Bs[BK][BN];

    const float* A = g_hB;
    const int M = N_NODES;

    int tid = threadIdx.x;
    int tx = tid & 15;
    int ty = tid >> 4;
    int rowBase = blockIdx.x * BM;

    float acc[TM][TN];
#pragma unroll
    for (int m = 0; m < TM; m++)
#pragma unroll
        for (int n = 0; n < TN; n++) acc[m][n] = 0.0f;

    for (int k0 = 0; k0 < K; k0 += BK) {
#pragma unroll
        for (int i = 0; i < 4; i++) {
            int idx = tid + i * 256;
            int r   = idx >> 3;
            int k4  = idx & 7;
            int grow = rowBase + r;
            float4 v = make_float4(0.f, 0.f, 0.f, 0.f);
            if (grow < M)
                v = *reinterpret_cast<const float4*>(&A[(size_t)grow * K + k0 + k4 * 4]);
            v.x = fmaxf(v.x, 0.f); v.y = fmaxf(v.y, 0.f);
            v.z = fmaxf(v.z, 0.f); v.w = fmaxf(v.w, 0.f);
            As[k4 * 4 + 0][r] = v.x;
            As[k4 * 4 + 1][r] = v.y;
            As[k4 * 4 + 2][r] = v.z;
            As[k4 * 4 + 3][r] = v.w;
        }
#pragma unroll
        for (int i = 0; i < 2; i++) {
            int idx = tid + i * 256;
            int r = idx >> 4;
            int c4 = idx & 15;
            *reinterpret_cast<float4*>(&Bs[r][c4 * 4]) =
                *reinterpret_cast<const float4*>(&B[(size_t)(k0 + r) * BN + c4 * 4]);
        }
        __syncthreads();

#pragma unroll
        for (int k = 0; k < BK; k++) {
            float a[TM], b[TN];
#pragma unroll
            for (int m = 0; m < TM; m++) a[m] = As[k][ty * TM + m];
#pragma unroll
            for (int n = 0; n < TN; n++) b[n] = Bs[k][tx * TN + n];
#pragma unroll
            for (int m = 0; m < TM; m++)
#pragma unroll
                for (int n = 0; n < TN; n++) acc[m][n] = fmaf(a[m], b[n], acc[m][n]);
        }
        __syncthreads();
    }

#pragma unroll
    for (int m = 0; m < TM; m++) {
        int grow = rowBase + ty * TM + m;
        if (grow < M) {
            float4 v = make_float4(acc[m][0], acc[m][1], acc[m][2], acc[m][3]);
            *reinterpret_cast<float4*>(&g_hA[(size_t)grow * BN + tx * TN]) = v;
        }
    }
}

// -------- pull aggregation: one warp per dst row --------

template <bool FUSE_FC>
__global__ void __launch_bounds__(256)
k_pull(const float* __restrict__ bias, const float* __restrict__ Wfc,
       const float* __restrict__ bfc, float* __restrict__ out) {
    int lane = threadIdx.x & 31;
    int row = blockIdx.x * 8 + (threadIdx.x >> 5);
    if (row >= N_NODES) return;

    float di = g_dinv[row];
    float c = di * di;
    const float* hr = &g_hA[(size_t)row * HID];
    float a0 = fmaf(hr[lane],      c, bias[lane]);
    float a1 = fmaf(hr[lane + 32], c, bias[lane + 32]);

    int start = g_rowptr[row];
    int end   = g_rowptr[row + 1];
    for (int i = start; i < end; i += 32) {
        int n = min(32, end - i);
        int2 pk = make_int2(0, 0);
        if (i + lane < end) pk = g_epack[i + lane];
        for (int j = 0; j < n; j++) {
            int   s  = __shfl_sync(~0u, pk.x, j);
            float nm = __int_as_float(__shfl_sync(~0u, pk.y, j));
            const float* hs = &g_hA[(size_t)s * HID];
            a0 = fmaf(hs[lane],      nm, a0);
            a1 = fmaf(hs[lane + 32], nm, a1);
        }
    }

    if (!FUSE_FC) {
        g_hB[(size_t)row * HID + lane]      = a0;
        g_hB[(size_t)row * HID + lane + 32] = a1;
    } else {
        a0 = fmaxf(a0, 0.f);
        a1 = fmaxf(a1, 0.f);
        float res[OUT_DIM];
#pragma unroll
        for (int k = 0; k < OUT_DIM; k++) {
            float p = a0 * __ldg(&Wfc[lane * OUT_DIM + k]) +
                      a1 * __ldg(&Wfc[(lane + 32) * OUT_DIM + k]);
#pragma unroll
            for (int o = 16; o > 0; o >>= 1) p += __shfl_xor_sync(~0u, p, o);
            res[k] = p;
        }
        if (lane < OUT_DIM)
            out[(size_t)row * OUT_DIM + lane] = res[lane] + bfc[lane];
    }
}

// ---------------- launcher ----------------
// DAG: CSR-build chain (L2/atomic-bound) runs concurrently with GEMM1
// (tensor-bound) on a second stream; both join before pull1.
// Streams/events are created lazily on the first call (the uncaptured
// correctness run), so nothing is created during graph capture.

extern "C" void kernel_launch(void* const* d_in, const int* in_sizes, int n_in,
                              void* d_out, int out_size) {
    const float* x   = (const float*)d_in[0];
    const int*   ei  = (const int*)d_in[1];    // int32 (JAX x64 disabled)
    const float* ew  = (const float*)d_in[2];
    const float* W1  = (const float*)d_in[3];
    const float* b1  = (const float*)d_in[4];
    const float* W2  = (const float*)d_in[5];
    const float* b2  = (const float*)d_in[6];
    const float* Wfc = (const float*)d_in[7];
    const float* bfc = (const float*)d_in[8];
    float* out = (float*)d_out;

    static cudaStream_t s1 = nullptr;
    static cudaEvent_t evFork = nullptr, evJoin = nullptr;
    if (!s1) {
        cudaStreamCreateWithFlags(&s1, cudaStreamNonBlocking);
        cudaEventCreateWithFlags(&evFork, cudaEventDisableTiming);
        cudaEventCreateWithFlags(&evJoin, cudaEventDisableTiming);
    }

    const int T = 256;
    int gbN    = (N_NODES + T - 1) / T;
    int gbE    = (N_EDGES + T - 1) / T;
    int gbGemm = (N_NODES + 127) / 128;
    int gbPull = (N_NODES + 7) / 8;

    // Fork: GEMM1 on s1, CSR build on the main (capture) stream.
    cudaEventRecord(evFork, 0);
    cudaStreamWaitEvent(s1, evFork, 0);
    k_gemm_tf32<<<gbGemm, T, 0, s1>>>(x, W1, IN_DIM);
    cudaEventRecord(evJoin, s1);

    k_init<<<gbN, T>>>();
    k_accum_deg<<<gbE, T>>>(ei, ew);
    k_rsqrt<<<gbN, T>>>();
    k_scan1<<<NBLK, SB>>>();
    k_scan2<<<1, 32>>>();
    k_scan3<<<NBLK, SB>>>();
    k_fill<<<gbE, T>>>(ei, ew);

    // Join: pull1 needs both hA (s1) and the CSR (main stream).
    cudaStreamWaitEvent((cudaStream_t)0, evJoin, 0);

    k_pull<false><<<gbPull, T>>>(b1, nullptr, nullptr, nullptr);

    // layer 2 + fused FC
    k_gemm64<<<gbGemm, T>>>(W2, HID);
    k_pull<true><<<gbPull, T>>>(b2, Wfc, bfc, out);
}

// round 11
// speedup vs baseline: 2.3266x; 1.0581x over previous
#include <cuda_runtime.h>
#include <cuda_bf16.h>
#include <cstdint>

#define N_NODES 100000
#define N_EDGES 3200000
#define IN_DIM  512
#define HID     64
#define OUT_DIM 5

#define SB 1024
#define NBLK ((N_NODES + SB - 1) / SB)   // 98

// Scratch (allocation-free rule): __device__ globals, device-code refs only.
__device__ __align__(16) float g_dinv[N_NODES];
__device__ __align__(16) float g_hA[(size_t)N_NODES * HID];
__device__ __align__(16) float g_hB[(size_t)N_NODES * HID];
// CSR (dst-binned), rebuilt each launch, shared by both layers.
__device__ int  g_cnt[N_NODES];
__device__ int  g_rowptr[N_NODES + 1];
__device__ int  g_cursor[N_NODES];
__device__ int  g_bsum[NBLK];
__device__ __align__(8) int2 g_epack[N_EDGES];   // {src, bitcast(norm)}

// ---------------- degree + incoming-count ----------------

__global__ void k_init() {
    int i = blockIdx.x * blockDim.x + threadIdx.x;
    if (i < N_NODES) { g_dinv[i] = 1.0f; g_cnt[i] = 0; }
}

__global__ void k_accum_deg(const int* __restrict__ ei,
                            const float* __restrict__ ew) {
    int e = blockIdx.x * blockDim.x + threadIdx.x;
    if (e < N_EDGES) {
        int d = ei[N_EDGES + e];
        atomicAdd(&g_dinv[d], ew[e]);
        atomicAdd(&g_cnt[d], 1);
    }
}

__global__ void k_rsqrt() {
    int i = blockIdx.x * blockDim.x + threadIdx.x;
    if (i < N_NODES) g_dinv[i] = rsqrtf(g_dinv[i]);
}

// ---------------- multi-block 3-phase prefix scan ----------------

__global__ void __launch_bounds__(SB) k_scan1() {
    __shared__ int ws[32];
    int tid = threadIdx.x, lane = tid & 31, wid = tid >> 5;
    int i = blockIdx.x * SB + tid;
    int v = (i < N_NODES) ? g_cnt[i] : 0;
    int x = v;
#pragma unroll
    for (int o = 1; o < 32; o <<= 1) {
        int y = __shfl_up_sync(~0u, x, o);
        if (lane >= o) x += y;
    }
    if (lane == 31) ws[wid] = x;
    __syncthreads();
    if (wid == 0) {
        int w = ws[lane];
#pragma unroll
        for (int o = 1; o < 32; o <<= 1) {
            int y = __shfl_up_sync(~0u, w, o);
            if (lane >= o) w += y;
        }
        ws[lane] = w;
    }
    __syncthreads();
    int incl = x + (wid > 0 ? ws[wid - 1] : 0);
    if (i < N_NODES) g_rowptr[i + 1] = incl;
    if (tid == SB - 1) g_bsum[blockIdx.x] = incl;
}

__global__ void k_scan2() {
    int lane = threadIdx.x;
    int carry = 0;
    for (int base = 0; base < NBLK; base += 32) {
        int v = (base + lane < NBLK) ? g_bsum[base + lane] : 0;
        int x = v;
#pragma unroll
        for (int o = 1; o < 32; o <<= 1) {
            int y = __shfl_up_sync(~0u, x, o);
            if (lane >= o) x += y;
        }
        if (base + lane < NBLK) g_bsum[base + lane] = x - v + carry;
        carry += __shfl_sync(~0u, x, 31);
    }
}

__global__ void __launch_bounds__(SB) k_scan3() {
    int i = blockIdx.x * SB + threadIdx.x;
    if (i >= N_NODES) return;
    int off = g_bsum[i >> 10];
    int r = g_rowptr[i + 1] + off;
    g_rowptr[i + 1] = r;
    g_cursor[i] = r - g_cnt[i];
    if (i == 0) g_rowptr[0] = 0;
}

// ---------------- CSR fill ----------------

__global__ void k_fill(const int* __restrict__ ei, const float* __restrict__ ew) {
    int e = blockIdx.x * blockDim.x + threadIdx.x;
    if (e >= N_EDGES) return;
    int s = ei[e];
    int d = ei[N_EDGES + e];
    float nm = g_dinv[s] * ew[e] * g_dinv[d];
    int pos = atomicAdd(&g_cursor[d], 1);
    g_epack[pos] = make_int2(s, __float_as_int(nm));
}

// ---------------- bf16 split helpers ----------------
// v = hi + lo with hi, lo bf16; missing lo*lo term ~2^-18 per product.

__device__ __forceinline__ void split_bf2(float v0, float v1,
                                          uint32_t& h, uint32_t& l) {
    __nv_bfloat16 b0 = __float2bfloat16(v0);
    __nv_bfloat16 b1 = __float2bfloat16(v1);
    __nv_bfloat162 hp = __halves2bfloat162(b0, b1);   // b0 in low 16 bits
    h = *reinterpret_cast<uint32_t*>(&hp);
    float r0 = v0 - __bfloat162float(b0);
    float r1 = v1 - __bfloat162float(b1);
    asm("cvt.rn.bf16x2.f32 %0, %1, %2;" : "=r"(l) : "f"(r1), "f"(r0));
}

__device__ __forceinline__ void mma_bf16(float* c, const uint32_t* a, const uint32_t* b) {
    asm volatile(
        "mma.sync.aligned.m16n8k16.row.col.f32.bf16.bf16.f32 "
        "{%0,%1,%2,%3}, {%4,%5,%6,%7}, {%8,%9}, {%0,%1,%2,%3};"
        : "+f"(c[0]), "+f"(c[1]), "+f"(c[2]), "+f"(c[3])
        : "r"(a[0]), "r"(a[1]), "r"(a[2]), "r"(a[3]), "r"(b[0]), "r"(b[1]));
}

__device__ __forceinline__ void cp16(uint32_t dst, const void* src, bool valid) {
    asm volatile("cp.async.cg.shared.global [%0], [%1], 16, %2;"
                 :: "r"(dst), "l"(src), "r"(valid ? 16 : 0) : "memory");
}

// ------- 3xBF16 tensor-core GEMM (layer 1): g_hA = x @ W1, K=512 -------
// Block 128x64, 8 warps 4(m)x2(n), warp tile 32x32, BK=16 = one k16 MMA group.
// cp.async double-buffered raw-f32 tiles; hi/lo bf16 split at fragment load.

#define APITCH 20
#define BPITCH 72

__global__ void __launch_bounds__(256)
k_gemm_bf16(const float* __restrict__ A, const float* __restrict__ B, int K) {
    __shared__ float As[2][128 * APITCH];
    __shared__ float Bs[2][16 * BPITCH];

    const int M = N_NODES;
    int tid  = threadIdx.x;
    int wid  = tid >> 5;
    int lane = tid & 31;
    int wm = wid >> 1, wn = wid & 1;
    int qr = lane >> 2, qc = lane & 3;
    int rowBase = blockIdx.x * 128;

    int ar0 = tid >> 2,         ac0 = (tid & 3) * 4;
    int ar1 = (tid >> 2) + 64,  ac1 = ac0;
    int brr = tid >> 4,         bcc = (tid & 15) * 4;

    uint32_t sA0[2], sA1[2], sB0[2];
#pragma unroll
    for (int b = 0; b < 2; b++) {
        sA0[b] = (uint32_t)__cvta_generic_to_shared(&As[b][ar0 * APITCH + ac0]);
        sA1[b] = (uint32_t)__cvta_generic_to_shared(&As[b][ar1 * APITCH + ac1]);
        sB0[b] = (uint32_t)__cvta_generic_to_shared(&Bs[b][brr * BPITCH + bcc]);
    }

    auto loadTiles = [&](int k0, int buf) {
        int g0 = rowBase + ar0, g1 = rowBase + ar1;
        bool v0 = g0 < M, v1 = g1 < M;
        cp16(sA0[buf], &A[(size_t)(v0 ? g0 : 0) * K + k0 + ac0], v0);
        cp16(sA1[buf], &A[(size_t)(v1 ? g1 : 0) * K + k0 + ac1], v1);
        cp16(sB0[buf], &B[(size_t)(k0 + brr) * HID + bcc], true);
        asm volatile("cp.async.commit_group;" ::: "memory");
    };

    float acc[2][4][4];
#pragma unroll
    for (int mt = 0; mt < 2; mt++)
#pragma unroll
        for (int nt = 0; nt < 4; nt++)
#pragma unroll
            for (int i = 0; i < 4; i++) acc[mt][nt][i] = 0.0f;

    const int NIT = K / 16;   // 32
    loadTiles(0, 0);

    for (int it = 0; it < NIT; it++) {
        int buf = it & 1;
        if (it + 1 < NIT) {
            loadTiles((it + 1) * 16, buf ^ 1);
            asm volatile("cp.async.wait_group 1;" ::: "memory");
        } else {
            asm volatile("cp.async.wait_group 0;" ::: "memory");
        }
        __syncthreads();

        const float* as = As[buf];
        const float* bs = Bs[buf];

        // A fragments: m16n8k16 row-major. a0:(qr, 2qc..+1) a1:(qr+8, same)
        // a2:(qr, 2qc+8..+9) a3:(qr+8, same). k-pairs adjacent -> float2.
        uint32_t fah[2][4], fal[2][4];
#pragma unroll
        for (int mt = 0; mt < 2; mt++) {
            int r0 = wm * 32 + mt * 16 + qr;
            int c0 = 2 * qc;
            float2 p0 = *reinterpret_cast<const float2*>(&as[r0 * APITCH + c0]);
            float2 p1 = *reinterpret_cast<const float2*>(&as[(r0 + 8) * APITCH + c0]);
            float2 p2 = *reinterpret_cast<const float2*>(&as[r0 * APITCH + c0 + 8]);
            float2 p3 = *reinterpret_cast<const float2*>(&as[(r0 + 8) * APITCH + c0 + 8]);
            split_bf2(p0.x, p0.y, fah[mt][0], fal[mt][0]);
            split_bf2(p1.x, p1.y, fah[mt][1], fal[mt][1]);
            split_bf2(p2.x, p2.y, fah[mt][2], fal[mt][2]);
            split_bf2(p3.x, p3.y, fah[mt][3], fal[mt][3]);
        }
        // B fragments: col-major 16x8. b0:(k 2qc..+1, col qr) b1:(k +8)
        uint32_t fbh[4][2], fbl[4][2];
#pragma unroll
        for (int nt = 0; nt < 4; nt++) {
            int col = wn * 32 + nt * 8 + qr;
            float v0 = bs[(2 * qc) * BPITCH + col];
            float v1 = bs[(2 * qc + 1) * BPITCH + col];
            float v2 = bs[(2 * qc + 8) * BPITCH + col];
            float v3 = bs[(2 * qc + 9) * BPITCH + col];
            split_bf2(v0, v1, fbh[nt][0], fbl[nt][0]);
            split_bf2(v2, v3, fbh[nt][1], fbl[nt][1]);
        }
#pragma unroll
        for (int mt = 0; mt < 2; mt++)
#pragma unroll
            for (int nt = 0; nt < 4; nt++) {
                mma_bf16(acc[mt][nt], fah[mt], fbh[nt]);   // hi*hi
                mma_bf16(acc[mt][nt], fah[mt], fbl[nt]);   // hi*lo
                mma_bf16(acc[mt][nt], fal[mt], fbh[nt]);   // lo*hi
            }
        __syncthreads();
    }

    // epilogue: c0 (r, 2qc), c1 (r, 2qc+1), c2 (r+8, 2qc), c3 (r+8, 2qc+1)
#pragma unroll
    for (int mt = 0; mt < 2; mt++) {
#pragma unroll
        for (int nt = 0; nt < 4; nt++) {
            int r  = rowBase + wm * 32 + mt * 16 + qr;
            int cc = wn * 32 + nt * 8 + qc * 2;
            if (r < M)
                *reinterpret_cast<float2*>(&g_hA[(size_t)r * HID + cc]) =
                    make_float2(acc[mt][nt][0], acc[mt][nt][1]);
            if (r + 8 < M)
                *reinterpret_cast<float2*>(&g_hA[(size_t)(r + 8) * HID + cc]) =
                    make_float2(acc[mt][nt][2], acc[mt][nt][3]);
        }
    }
}

// ------- FFMA GEMM (layer 2, K=64): g_hA = relu(g_hB) @ W2 -------

__global__ void __launch_bounds__(256)
k_gemm64(const float* __restrict__ B, int K) {
    const int BM = 128, BN = 64, BK = 32, TM = 8, TN = 4;
    __shared__ float As[BK][BM];
    __shared__ float Bs[BK][BN];

    const float* A = g_hB;
    const int M = N_NODES;

    int tid = threadIdx.x;
    int tx = tid & 15;
    int ty = tid >> 4;
    int rowBase = blockIdx.x * BM;

    float acc[TM][TN];
#pragma unroll
    for (int m = 0; m < TM; m++)
#pragma unroll
        for (int n = 0; n < TN; n++) acc[m][n] = 0.0f;

    for (int k0 = 0; k0 < K; k0 += BK) {
#pragma unroll
        for (int i = 0; i < 4; i++) {
            int idx = tid + i * 256;
            int r   = idx >> 3;
            int k4  = idx & 7;
            int grow = rowBase + r;
            float4 v = make_float4(0.f, 0.f, 0.f, 0.f);
            if (grow < M)
                v = *reinterpret_cast<const float4*>(&A[(size_t)grow * K + k0 + k4 * 4]);
            v.x = fmaxf(v.x, 0.f); v.y = fmaxf(v.y, 0.f);
            v.z = fmaxf(v.z, 0.f); v.w = fmaxf(v.w, 0.f);
            As[k4 * 4 + 0][r] = v.x;
            As[k4 * 4 + 1][r] = v.y;
            As[k4 * 4 + 2][r] = v.z;
            As[k4 * 4 + 3][r] = v.w;
        }
#pragma unroll
        for (int i = 0; i < 2; i++) {
            int idx = tid + i * 256;
            int r = idx >> 4;
            int c4 = idx & 15;
            *reinterpret_cast<float4*>(&Bs[r][c4 * 4]) =
                *reinterpret_cast<const float4*>(&B[(size_t)(k0 + r) * BN + c4 * 4]);
        }
        __syncthreads();

#pragma unroll
        for (int k = 0; k < BK; k++) {
            float a[TM], b[TN];
#pragma unroll
            for (int m = 0; m < TM; m++) a[m] = As[k][ty * TM + m];
#pragma unroll
            for (int n = 0; n < TN; n++) b[n] = Bs[k][tx * TN + n];
#pragma unroll
            for (int m = 0; m < TM; m++)
#pragma unroll
                for (int n = 0; n < TN; n++) acc[m][n] = fmaf(a[m], b[n], acc[m][n]);
        }
        __syncthreads();
    }

#pragma unroll
    for (int m = 0; m < TM; m++) {
        int grow = rowBase + ty * TM + m;
        if (grow < M) {
            float4 v = make_float4(acc[m][0], acc[m][1], acc[m][2], acc[m][3]);
            *reinterpret_cast<float4*>(&g_hA[(size_t)grow * BN + tx * TN]) = v;
        }
    }
}

// -------- pull aggregation: one warp per dst row --------

template <bool FUSE_FC>
__global__ void __launch_bounds__(256)
k_pull(const float* __restrict__ bias, const float* __restrict__ Wfc,
       const float* __restrict__ bfc, float* __restrict__ out) {
    int lane = threadIdx.x & 31;
    int row = blockIdx.x * 8 + (threadIdx.x >> 5);
    if (row >= N_NODES) return;

    float di = g_dinv[row];
    float c = di * di;
    const float* hr = &g_hA[(size_t)row * HID];
    float a0 = fmaf(hr[lane],      c, bias[lane]);
    float a1 = fmaf(hr[lane + 32], c, bias[lane + 32]);

    int start = g_rowptr[row];
    int end   = g_rowptr[row + 1];
    for (int i = start; i < end; i += 32) {
        int n = min(32, end - i);
        int2 pk = make_int2(0, 0);
        if (i + lane < end) pk = g_epack[i + lane];
        for (int j = 0; j < n; j++) {
            int   s  = __shfl_sync(~0u, pk.x, j);
            float nm = __int_as_float(__shfl_sync(~0u, pk.y, j));
            const float* hs = &g_hA[(size_t)s * HID];
            a0 = fmaf(hs[lane],      nm, a0);
            a1 = fmaf(hs[lane + 32], nm, a1);
        }
    }

    if (!FUSE_FC) {
        g_hB[(size_t)row * HID + lane]      = a0;
        g_hB[(size_t)row * HID + lane + 32] = a1;
    } else {
        a0 = fmaxf(a0, 0.f);
        a1 = fmaxf(a1, 0.f);
        float res[OUT_DIM];
#pragma unroll
        for (int k = 0; k < OUT_DIM; k++) {
            float p = a0 * __ldg(&Wfc[lane * OUT_DIM + k]) +
                      a1 * __ldg(&Wfc[(lane + 32) * OUT_DIM + k]);
#pragma unroll
            for (int o = 16; o > 0; o >>= 1) p += __shfl_xor_sync(~0u, p, o);
            res[k] = p;
        }
        if (lane < OUT_DIM)
            out[(size_t)row * OUT_DIM + lane] = res[lane] + bfc[lane];
    }
}

// ---------------- launcher ----------------
// DAG: CSR-build chain (L2/atomic-bound) concurrent with GEMM1 (tensor-bound).

extern "C" void kernel_launch(void* const* d_in, const int* in_sizes, int n_in,
                              void* d_out, int out_size) {
    const float* x   = (const float*)d_in[0];
    const int*   ei  = (const int*)d_in[1];    // int32 (JAX x64 disabled)
    const float* ew  = (const float*)d_in[2];
    const float* W1  = (const float*)d_in[3];
    const float* b1  = (const float*)d_in[4];
    const float* W2  = (const float*)d_in[5];
    const float* b2  = (const float*)d_in[6];
    const float* Wfc = (const float*)d_in[7];
    const float* bfc = (const float*)d_in[8];
    float* out = (float*)d_out;

    static cudaStream_t s1 = nullptr;
    static cudaEvent_t evFork = nullptr, evJoin = nullptr;
    if (!s1) {
        cudaStreamCreateWithFlags(&s1, cudaStreamNonBlocking);
        cudaEventCreateWithFlags(&evFork, cudaEventDisableTiming);
        cudaEventCreateWithFlags(&evJoin, cudaEventDisableTiming);
    }

    const int T = 256;
    int gbN    = (N_NODES + T - 1) / T;
    int gbE    = (N_EDGES + T - 1) / T;
    int gbGemm = (N_NODES + 127) / 128;
    int gbPull = (N_NODES + 7) / 8;

    // Fork: GEMM1 on s1, CSR build on the main (capture) stream.
    cudaEventRecord(evFork, 0);
    cudaStreamWaitEvent(s1, evFork, 0);
    k_gemm_bf16<<<gbGemm, T, 0, s1>>>(x, W1, IN_DIM);
    cudaEventRecord(evJoin, s1);

    k_init<<<gbN, T>>>();
    k_accum_deg<<<gbE, T>>>(ei, ew);
    k_rsqrt<<<gbN, T>>>();
    k_scan1<<<NBLK, SB>>>();
    k_scan2<<<1, 32>>>();
    k_scan3<<<NBLK, SB>>>();
    k_fill<<<gbE, T>>>(ei, ew);

    // Join: pull1 needs both hA (s1) and the CSR (main stream).
    cudaStreamWaitEvent((cudaStream_t)0, evJoin, 0);

    k_pull<false><<<gbPull, T>>>(b1, nullptr, nullptr, nullptr);

    // layer 2 + fused FC
    k_gemm64<<<gbGemm, T>>>(W2, HID);
    k_pull<true><<<gbPull, T>>>(b2, Wfc, bfc, out);
}